// round 3
// baseline (speedup 1.0000x reference)
#include <cuda_runtime.h>
#include <math.h>

#define N     2048
#define NNZ   32768
#define KL    96
#define GRID  128
#define TPB   256
#define BK    8

// ---------------- scratch (device globals; zero-init; no allocation) -------
__device__ float g_A[N*N];
__device__ float g_C[N*N];
__device__ float g_CT[N*N];
__device__ float g_G[N*N];
__device__ float g_M[N*N];

__device__ float g_vals[NNZ];
__device__ int   g_rowptr[N+1];
__device__ int   g_cnt[N];
__device__ int   g_colidx[NNZ];
__device__ float g_csrval[NNZ];

__device__ float g_raw[2][N];          // raw (unnormalized) Lanczos w vectors
__device__ float g_part[GRID];
__device__ float g_alpha[KL];
__device__ float g_betav[KL];
__device__ volatile unsigned int g_arrive[GRID];
__device__ volatile unsigned int g_release;

// ---------------- CSR build ------------------------------------------------
__global__ void k_prep(const float* __restrict__ pred, const float* __restrict__ scl) {
    int i = blockIdx.x * blockDim.x + threadIdx.x;
    if (i < NNZ) g_vals[i] = pred[i] * scl[i];
    if (i < N)   g_cnt[i] = 0;
}
__global__ void k_count(const int* __restrict__ rows) {
    int i = blockIdx.x * blockDim.x + threadIdx.x;
    if (i < NNZ) atomicAdd(&g_cnt[rows[i]], 1);
}
__global__ void k_scan() {
    if (threadIdx.x == 0) {
        int s = 0;
        for (int i = 0; i < N; i++) { g_rowptr[i] = s; s += g_cnt[i]; }
        g_rowptr[N] = s;
    }
    __syncthreads();
    for (int i = threadIdx.x; i < N; i += blockDim.x) g_cnt[i] = g_rowptr[i];
}
__global__ void k_fill(const int* __restrict__ rows, const int* __restrict__ cols) {
    int i = blockIdx.x * blockDim.x + threadIdx.x;
    if (i < NNZ) {
        int p = atomicAdd(&g_cnt[rows[i]], 1);
        g_colidx[p] = cols[i];
        g_csrval[p] = g_vals[i];
    }
}

// ---------------- SYRK: A = Af*Af^T / N + I (exactly symmetric) ------------
__global__ void __launch_bounds__(256) k_syrk(const float* __restrict__ Af) {
    int bx = blockIdx.x, by = blockIdx.y;
    if (bx < by) return;
    __shared__ __align__(16) float As[BK][132];
    __shared__ __align__(16) float Bs[BK][132];
    int tid = threadIdx.x;
    int tx = tid & 15, ty = tid >> 4;
    int row0 = by * 128, col0 = bx * 128;

    float acc[8][8];
#pragma unroll
    for (int i = 0; i < 8; i++)
#pragma unroll
        for (int j = 0; j < 8; j++) acc[i][j] = 0.f;

    int lr = tid >> 1;
    int lk = (tid & 1) * 4;
    const float* abase = Af + (size_t)(row0 + lr) * N + lk;
    const float* bbase = Af + (size_t)(col0 + lr) * N + lk;
    float4 pa = *(const float4*)abase;
    float4 pb = *(const float4*)bbase;

    for (int kk = 0; kk < N; kk += BK) {
        __syncthreads();
        As[lk+0][lr]=pa.x; As[lk+1][lr]=pa.y; As[lk+2][lr]=pa.z; As[lk+3][lr]=pa.w;
        Bs[lk+0][lr]=pb.x; Bs[lk+1][lr]=pb.y; Bs[lk+2][lr]=pb.z; Bs[lk+3][lr]=pb.w;
        __syncthreads();
        if (kk + BK < N) {
            pa = *(const float4*)(abase + kk + BK);
            pb = *(const float4*)(bbase + kk + BK);
        }
#pragma unroll
        for (int k = 0; k < BK; k++) {
            float4 a0 = *(const float4*)&As[k][4*ty];
            float4 a1 = *(const float4*)&As[k][64+4*ty];
            float4 b0 = *(const float4*)&Bs[k][4*tx];
            float4 b1 = *(const float4*)&Bs[k][64+4*tx];
            float av[8] = {a0.x,a0.y,a0.z,a0.w,a1.x,a1.y,a1.z,a1.w};
            float bv[8] = {b0.x,b0.y,b0.z,b0.w,b1.x,b1.y,b1.z,b1.w};
#pragma unroll
            for (int i = 0; i < 8; i++)
#pragma unroll
                for (int j = 0; j < 8; j++) acc[i][j] += av[i]*bv[j];
        }
    }
    float invn = 1.0f / (float)N;
#pragma unroll
    for (int i = 0; i < 8; i++) {
        int gi = row0 + ((i<4) ? (4*ty+i) : (64+4*ty+i-4));
#pragma unroll
        for (int j = 0; j < 8; j++) {
            int gj = col0 + ((j<4) ? (4*tx+j) : (64+4*tx+j-4));
            float val = acc[i][j]*invn + ((gi==gj)?1.0f:0.0f);
            g_A[(size_t)gi*N+gj] = val;
            if (bx > by) g_A[(size_t)gj*N+gi] = val;
        }
    }
}

// ---------------- SpMM: Y = S * X -------------------------------------------
__device__ __forceinline__ void spmm_body(const float* __restrict__ X, float* __restrict__ Y) {
    int r = blockIdx.x, t = threadIdx.x;
    int s = g_rowptr[r], e = g_rowptr[r+1];
    float acc[8] = {0,0,0,0,0,0,0,0};
    for (int k = s; k < e; k++) {
        int c = g_colidx[k];
        float v = g_csrval[k];
        const float* xr = X + (size_t)c * N;
#pragma unroll
        for (int u = 0; u < 8; u++) acc[u] += v * xr[t + u*TPB];
    }
    float* yr = Y + (size_t)r * N;
#pragma unroll
    for (int u = 0; u < 8; u++) yr[t + u*TPB] = acc[u];
}
__global__ void k_spmm_AC()  { spmm_body(g_A,  g_C); }
__global__ void k_spmm_CTG() { spmm_body(g_CT, g_G); }

// ---------------- transpose --------------------------------------------------
__device__ __forceinline__ void tr_body(const float* __restrict__ in, float* __restrict__ out) {
    __shared__ float t[32][33];
    int bx = blockIdx.x*32, by = blockIdx.y*32;
    int x = bx + threadIdx.x;
#pragma unroll
    for (int j = 0; j < 32; j += 8)
        t[threadIdx.y+j][threadIdx.x] = in[(size_t)(by+threadIdx.y+j)*N + x];
    __syncthreads();
    int x2 = by + threadIdx.x;
#pragma unroll
    for (int j = 0; j < 32; j += 8)
        out[(size_t)(bx+threadIdx.y+j)*N + x2] = t[threadIdx.x][threadIdx.y+j];
}
__global__ void k_tr_C_CT() { tr_body(g_C, g_CT); }
__global__ void k_tr_C_G()  { tr_body(g_C, g_G); }

// ---------------- elementwise ------------------------------------------------
__global__ void k_combine() {   // g_C = A + C + C^T + G
    int i = blockIdx.x*blockDim.x + threadIdx.x;
    float4 a = ((const float4*)g_A)[i];
    float4 c = ((const float4*)g_C)[i];
    float4 t = ((const float4*)g_CT)[i];
    float4 g = ((const float4*)g_G)[i];
    float4 r; r.x=a.x+c.x+t.x+g.x; r.y=a.y+c.y+t.y+g.y;
    r.z=a.z+c.z+t.z+g.z; r.w=a.w+c.w+t.w+g.w;
    ((float4*)g_C)[i] = r;
}
__global__ void k_sym() {       // g_M = 0.5*(C + C^T)  (g_G holds C^T)
    int i = blockIdx.x*blockDim.x + threadIdx.x;
    float4 c = ((const float4*)g_C)[i];
    float4 g = ((const float4*)g_G)[i];
    float4 r; r.x=0.5f*(c.x+g.x); r.y=0.5f*(c.y+g.y);
    r.z=0.5f*(c.z+g.z); r.w=0.5f*(c.w+g.w);
    ((float4*)g_M)[i] = r;
}

// ---------------- Lanczos (persistent, 2 grid barriers / iter) --------------
__global__ void k_reset() {
    int t = threadIdx.x;
    if (t < GRID) g_arrive[t] = 0;
    if (t == 0)   g_release = 0;
}

__device__ __forceinline__ void gbar(unsigned int& ep) {
    ep++;
    __threadfence();
    __syncthreads();
    if (blockIdx.x == 0) {
        if (threadIdx.x > 0 && threadIdx.x < GRID) {
            while (g_arrive[threadIdx.x] < ep) __nanosleep(20);
        }
        __syncthreads();
        if (threadIdx.x == 0) g_release = ep;
    } else {
        if (threadIdx.x == 0) {
            g_arrive[blockIdx.x] = ep;
            while (g_release < ep) __nanosleep(20);
        }
    }
    __syncthreads();
    __threadfence();
}

__device__ __forceinline__ float sum_parts(float* sred, float* sbc) {
    int tid = threadIdx.x, warp = tid >> 5, wl = tid & 31;
    float a = (tid < GRID) ? __ldcg(&g_part[tid]) : 0.f;
#pragma unroll
    for (int off = 16; off; off >>= 1) a += __shfl_down_sync(0xffffffffu, a, off);
    if (wl == 0) sred[warp] = a;
    __syncthreads();
    if (tid == 0) {
        float s = 0.f;
#pragma unroll
        for (int w = 0; w < 4; w++) s += sred[w];   // GRID=128 -> warps 0..3
        sbc[0] = s;
    }
    __syncthreads();
    return sbc[0];
}

__global__ void __launch_bounds__(TPB) k_lanczos() {
    __shared__ __align__(16) float sv[N];
    __shared__ float shw[16];
    __shared__ float sred[8];
    __shared__ float sbc[1];

    const int tid = threadIdx.x, bid = blockIdx.x;
    const int q = tid >> 4, lane = tid & 15;
    const int row = bid*16 + q;
    const int myrow = bid*16 + tid;     // valid for tid < 16
    const int warp = tid >> 5, wl = tid & 31;
    unsigned int ep = 0;

    // ---- deterministic start vector (raw), compute its norm
    float initx = 0.f;
    if (tid < 16) {
        unsigned int h = (unsigned int)myrow * 2654435761u + 0x9E3779B9u;
        h ^= h>>16; h *= 0x85ebca6bu; h ^= h>>13; h *= 0xc2b2ae35u; h ^= h>>16;
        initx = (float)(h & 0xffffu) * (1.0f/65536.0f) + 0.0625f;
        g_raw[0][myrow] = initx;
    }
    {
        float p = (tid < 16) ? initx*initx : 0.f;
#pragma unroll
        for (int off = 8; off; off >>= 1) p += __shfl_down_sync(0xffffffffu, p, off, 16);
        if (tid == 0) g_part[bid] = p;
        gbar(ep);
    }
    float nrm = sum_parts(sred, sbc);
    float invb_cur = rsqrtf(nrm);
    float invb_prev = 0.f, beta_prev = 0.f;
    int cur = 0;

    for (int j = 0; j < KL; j++) {
        // stage normalized v_j into shared
        for (int i = tid; i < N; i += TPB) sv[i] = __ldcg(&g_raw[cur][i]) * invb_cur;
        __syncthreads();

        // matvec u = M v_j  (16 rows/block, 16 lanes/row)
        const float4* M4  = ((const float4*)g_M) + (size_t)row * (N/4);
        const float4* sv4 = (const float4*)sv;
        float s = 0.f;
#pragma unroll
        for (int t = 0; t < 16; t++) {
            int qi = lane*2 + t*32;
            float4 m0 = M4[qi], m1 = M4[qi+1];
            float4 x0 = sv4[qi], x1 = sv4[qi+1];
            s += m0.x*x0.x + m0.y*x0.y + m0.z*x0.z + m0.w*x0.w
               + m1.x*x1.x + m1.y*x1.y + m1.z*x1.z + m1.w*x1.w;
        }
#pragma unroll
        for (int off = 8; off; off >>= 1) s += __shfl_down_sync(0xffffffffu, s, off, 16);

        float pa = 0.f;
        if (lane == 0) { shw[q] = s; pa = s * sv[row]; }
#pragma unroll
        for (int off = 16; off; off >>= 1) pa += __shfl_down_sync(0xffffffffu, pa, off);
        if (wl == 0) sred[warp] = pa;
        __syncthreads();
        if (tid == 0) {
            float sa = 0.f;
#pragma unroll
            for (int w = 0; w < 8; w++) sa += sred[w];
            g_part[bid] = sa;
        }
        gbar(ep);

        // alpha; w = u - alpha v - beta_prev v_prev  (own rows)
        float alpha = sum_parts(sred, sbc);
        if (bid == 0 && tid == 0) g_alpha[j] = alpha;
        float w = 0.f;
        if (tid < 16) {
            w = shw[tid] - alpha * sv[myrow]
              - beta_prev * invb_prev * g_raw[cur^1][myrow];
            g_raw[cur^1][myrow] = w;       // store raw w_j
        }
        float pw = (tid < 16) ? w*w : 0.f;
#pragma unroll
        for (int off = 8; off; off >>= 1) pw += __shfl_down_sync(0xffffffffu, pw, off, 16);
        if (tid == 0) g_part[bid] = pw;
        gbar(ep);

        float b2 = sum_parts(sred, sbc);
        float beta = sqrtf(fmaxf(b2, 1e-30f));
        if (bid == 0 && tid == 0) g_betav[j] = beta;
        beta_prev = beta;
        invb_prev = invb_cur;
        invb_cur = 1.0f / beta;
        cur ^= 1;
    }
}

// ---------------- tridiagonal extremes via Sturm bisection ------------------
__device__ int sturm_count(double x) {
    double d = (double)g_alpha[0] - x;
    int cnt = (d < 0.0);
    for (int i = 1; i < KL; i++) {
        double b = (double)g_betav[i-1];
        double den = d;
        if (fabs(den) < 1e-280) den = (den < 0.0) ? -1e-280 : 1e-280;
        d = ((double)g_alpha[i] - x) - b*b/den;
        cnt += (d < 0.0);
    }
    return cnt;
}

__global__ void k_extremes(float* out) {
    if (threadIdx.x != 0 || blockIdx.x != 0) return;
    double lo = 1e300, hi = -1e300;
    for (int i = 0; i < KL; i++) {
        double a  = (double)g_alpha[i];
        double bl = (i > 0)      ? fabs((double)g_betav[i-1]) : 0.0;
        double br = (i < KL-1)   ? fabs((double)g_betav[i])   : 0.0;
        if (a - bl - br < lo) lo = a - bl - br;
        if (a + bl + br > hi) hi = a + bl + br;
    }
    double l = lo, h = hi;
    for (int it = 0; it < 100; it++) {        // lambda_max
        double m = 0.5*(l+h);
        if (sturm_count(m) >= KL) h = m; else l = m;
    }
    double lmax = 0.5*(l+h);
    l = lo; h = hi;
    for (int it = 0; it < 100; it++) {        // lambda_min
        double m = 0.5*(l+h);
        if (sturm_count(m) >= 1) h = m; else l = m;
    }
    double lmin = 0.5*(l+h);
    const double eps = 1e-12;
    if (lmax < eps) lmax = eps;
    if (lmin < eps) lmin = eps;
    out[0] = (float)(log(lmax) - log(lmin));
}

// ---------------- launch ------------------------------------------------------
extern "C" void kernel_launch(void* const* d_in, const int* in_sizes, int n_in,
                              void* d_out, int out_size) {
    const float* pred = (const float*)d_in[0];
    const float* scl  = (const float*)d_in[1];
    const float* Af   = (const float*)d_in[2];
    const int* frows  = (const int*)d_in[3];
    const int* fcols  = (const int*)d_in[4];
    float* out = (float*)d_out;

    k_prep <<<NNZ/TPB, TPB>>>(pred, scl);
    k_count<<<NNZ/TPB, TPB>>>(frows);
    k_scan <<<1, TPB>>>();
    k_fill <<<NNZ/TPB, TPB>>>(frows, fcols);

    k_syrk<<<dim3(16,16), 256>>>(Af);

    k_spmm_AC <<<N, TPB>>>();
    k_tr_C_CT <<<dim3(64,64), dim3(32,8)>>>();
    k_spmm_CTG<<<N, TPB>>>();
    k_combine <<<N*N/4/TPB, TPB>>>();
    k_tr_C_G  <<<dim3(64,64), dim3(32,8)>>>();
    k_sym     <<<N*N/4/TPB, TPB>>>();

    k_reset   <<<1, TPB>>>();
    k_lanczos <<<GRID, TPB>>>();
    k_extremes<<<1, 32>>>(out);
}

// round 6
// speedup vs baseline: 7.2489x; 7.2489x over previous
#include <cuda_runtime.h>
#include <math.h>

#define N     2048
#define NNZ   32768
#define KL    96
#define GRID  128
#define TPB   256
#define BK    8

// ---------------- scratch (device globals; no allocation) ------------------
__device__ float g_A[N*N];
__device__ float g_C[N*N];
__device__ float g_CT[N*N];
__device__ float g_G[N*N];
__device__ float g_M[N*N];

__device__ float g_vals[NNZ];
__device__ int   g_rowptr[N+1];
__device__ int   g_cnt[N];
__device__ int   g_colidx[NNZ];
__device__ float g_csrval[NNZ];

__device__ float g_raw[2][N];
__device__ float g_partA[GRID];     // alpha partials
__device__ float g_partB[GRID];     // norm + beta partials
__device__ float g_alpha[KL];
__device__ float g_betav[KL];
__device__ volatile unsigned int g_arrive[GRID];
__device__ volatile unsigned int g_release;

// ---------------- CSR build ------------------------------------------------
__global__ void k_prep(const float* __restrict__ pred, const float* __restrict__ scl) {
    int i = blockIdx.x * blockDim.x + threadIdx.x;
    if (i < NNZ) g_vals[i] = pred[i] * scl[i];
    if (i < N)   g_cnt[i] = 0;
}
__global__ void k_count(const int* __restrict__ rows) {
    int i = blockIdx.x * blockDim.x + threadIdx.x;
    if (i < NNZ) atomicAdd(&g_cnt[rows[i]], 1);
}
// parallel exclusive scan of g_cnt[0..N) -> g_rowptr, copy back to g_cnt
__global__ void k_scan() {                     // 256 threads, 8 elems/thread
    int tid = threadIdx.x;
    int lane = tid & 31, warp = tid >> 5;
    int v[8]; int loc = 0;
#pragma unroll
    for (int u = 0; u < 8; u++) { v[u] = g_cnt[tid*8 + u]; loc += v[u]; }
    int sc = loc;
#pragma unroll
    for (int off = 1; off < 32; off <<= 1) {
        int nb = __shfl_up_sync(0xffffffffu, sc, off);
        if (lane >= off) sc += nb;
    }
    __shared__ int wsum[8];
    if (lane == 31) wsum[warp] = sc;
    __syncthreads();
    if (tid == 0) {
        int a = 0;
#pragma unroll
        for (int w = 0; w < 8; w++) { int t = wsum[w]; wsum[w] = a; a += t; }
    }
    __syncthreads();
    int run = sc - loc + wsum[warp];
#pragma unroll
    for (int u = 0; u < 8; u++) {
        g_rowptr[tid*8 + u] = run;
        g_cnt[tid*8 + u]    = run;
        run += v[u];
    }
    if (tid == 255) g_rowptr[N] = run;
}
__global__ void k_fill(const int* __restrict__ rows, const int* __restrict__ cols) {
    int i = blockIdx.x * blockDim.x + threadIdx.x;
    if (i < NNZ) {
        int p = atomicAdd(&g_cnt[rows[i]], 1);
        g_colidx[p] = cols[i];
        g_csrval[p] = g_vals[i];
    }
}

// ---------------- SYRK: A = Af*Af^T / N + I (exactly symmetric) ------------
__global__ void __launch_bounds__(256) k_syrk(const float* __restrict__ Af) {
    int bx = blockIdx.x, by = blockIdx.y;
    if (bx < by) return;
    __shared__ __align__(16) float As[BK][132];
    __shared__ __align__(16) float Bs[BK][132];
    int tid = threadIdx.x;
    int tx = tid & 15, ty = tid >> 4;
    int row0 = by * 128, col0 = bx * 128;

    float acc[8][8];
#pragma unroll
    for (int i = 0; i < 8; i++)
#pragma unroll
        for (int j = 0; j < 8; j++) acc[i][j] = 0.f;

    int lr = tid >> 1;
    int lk = (tid & 1) * 4;
    const float* abase = Af + (size_t)(row0 + lr) * N + lk;
    const float* bbase = Af + (size_t)(col0 + lr) * N + lk;
    float4 pa = *(const float4*)abase;
    float4 pb = *(const float4*)bbase;

    for (int kk = 0; kk < N; kk += BK) {
        __syncthreads();
        As[lk+0][lr]=pa.x; As[lk+1][lr]=pa.y; As[lk+2][lr]=pa.z; As[lk+3][lr]=pa.w;
        Bs[lk+0][lr]=pb.x; Bs[lk+1][lr]=pb.y; Bs[lk+2][lr]=pb.z; Bs[lk+3][lr]=pb.w;
        __syncthreads();
        if (kk + BK < N) {
            pa = *(const float4*)(abase + kk + BK);
            pb = *(const float4*)(bbase + kk + BK);
        }
#pragma unroll
        for (int k = 0; k < BK; k++) {
            float4 a0 = *(const float4*)&As[k][4*ty];
            float4 a1 = *(const float4*)&As[k][64+4*ty];
            float4 b0 = *(const float4*)&Bs[k][4*tx];
            float4 b1 = *(const float4*)&Bs[k][64+4*tx];
            float av[8] = {a0.x,a0.y,a0.z,a0.w,a1.x,a1.y,a1.z,a1.w};
            float bv[8] = {b0.x,b0.y,b0.z,b0.w,b1.x,b1.y,b1.z,b1.w};
#pragma unroll
            for (int i = 0; i < 8; i++)
#pragma unroll
                for (int j = 0; j < 8; j++) acc[i][j] += av[i]*bv[j];
        }
    }
    float invn = 1.0f / (float)N;
#pragma unroll
    for (int i = 0; i < 8; i++) {
        int gi = row0 + ((i<4) ? (4*ty+i) : (64+4*ty+i-4));
#pragma unroll
        for (int j = 0; j < 8; j++) {
            int gj = col0 + ((j<4) ? (4*tx+j) : (64+4*tx+j-4));
            float val = acc[i][j]*invn + ((gi==gj)?1.0f:0.0f);
            g_A[(size_t)gi*N+gj] = val;
            if (bx > by) g_A[(size_t)gj*N+gi] = val;
        }
    }
}

// ---------------- SpMM: Y = S * X -------------------------------------------
__device__ __forceinline__ void spmm_body(const float* __restrict__ X, float* __restrict__ Y) {
    int r = blockIdx.x, t = threadIdx.x;
    int s = g_rowptr[r], e = g_rowptr[r+1];
    float acc[8] = {0,0,0,0,0,0,0,0};
    for (int k = s; k < e; k++) {
        int c = g_colidx[k];
        float v = g_csrval[k];
        const float* xr = X + (size_t)c * N;
#pragma unroll
        for (int u = 0; u < 8; u++) acc[u] += v * xr[t + u*TPB];
    }
    float* yr = Y + (size_t)r * N;
#pragma unroll
    for (int u = 0; u < 8; u++) yr[t + u*TPB] = acc[u];
}
__global__ void k_spmm_AC()  { spmm_body(g_A,  g_C); }
__global__ void k_spmm_CTG() { spmm_body(g_CT, g_G); }

// ---------------- transpose --------------------------------------------------
__device__ __forceinline__ void tr_body(const float* __restrict__ in, float* __restrict__ out) {
    __shared__ float t[32][33];
    int bx = blockIdx.x*32, by = blockIdx.y*32;
    int x = bx + threadIdx.x;
#pragma unroll
    for (int j = 0; j < 32; j += 8)
        t[threadIdx.y+j][threadIdx.x] = in[(size_t)(by+threadIdx.y+j)*N + x];
    __syncthreads();
    int x2 = by + threadIdx.x;
#pragma unroll
    for (int j = 0; j < 32; j += 8)
        out[(size_t)(bx+threadIdx.y+j)*N + x2] = t[threadIdx.x][threadIdx.y+j];
}
__global__ void k_tr_C_CT() { tr_body(g_C, g_CT); }
__global__ void k_tr_C_G()  { tr_body(g_C, g_G); }

// ---------------- elementwise ------------------------------------------------
__global__ void k_combine() {   // g_C = A + C + C^T + G
    int i = blockIdx.x*blockDim.x + threadIdx.x;
    float4 a = ((const float4*)g_A)[i];
    float4 c = ((const float4*)g_C)[i];
    float4 t = ((const float4*)g_CT)[i];
    float4 g = ((const float4*)g_G)[i];
    float4 r; r.x=a.x+c.x+t.x+g.x; r.y=a.y+c.y+t.y+g.y;
    r.z=a.z+c.z+t.z+g.z; r.w=a.w+c.w+t.w+g.w;
    ((float4*)g_C)[i] = r;
}
__global__ void k_sym() {       // g_M = 0.5*(C + C^T)
    int i = blockIdx.x*blockDim.x + threadIdx.x;
    float4 c = ((const float4*)g_C)[i];
    float4 g = ((const float4*)g_G)[i];
    float4 r; r.x=0.5f*(c.x+g.x); r.y=0.5f*(c.y+g.y);
    r.z=0.5f*(c.z+g.z); r.w=0.5f*(c.w+g.w);
    ((float4*)g_M)[i] = r;
}

// ---------------- Lanczos (persistent, race-free two-buffer reductions) ----
__global__ void k_reset() {
    int t = threadIdx.x;
    if (t < GRID) g_arrive[t] = 0;
    if (t == 0)   g_release = 0;
}

__device__ __forceinline__ void gbar(unsigned int& ep) {
    ep++;
    __threadfence();
    __syncthreads();
    if (blockIdx.x == 0) {
        if (threadIdx.x > 0 && threadIdx.x < GRID) {
            while (g_arrive[threadIdx.x] < ep) __nanosleep(20);
        }
        __syncthreads();
        if (threadIdx.x == 0) g_release = ep;
    } else {
        if (threadIdx.x == 0) {
            g_arrive[blockIdx.x] = ep;
            while (g_release < ep) __nanosleep(20);
        }
    }
    __syncthreads();
    __threadfence();
}

__device__ __forceinline__ float sum_parts(const float* part, float* sred, float* sbc) {
    int tid = threadIdx.x, warp = tid >> 5, wl = tid & 31;
    float a = (tid < GRID) ? __ldcg(&part[tid]) : 0.f;
#pragma unroll
    for (int off = 16; off; off >>= 1) a += __shfl_down_sync(0xffffffffu, a, off);
    if (wl == 0) sred[warp] = a;
    __syncthreads();
    if (tid == 0) {
        float s = 0.f;
#pragma unroll
        for (int w = 0; w < 4; w++) s += sred[w];
        sbc[0] = s;
    }
    __syncthreads();
    return sbc[0];
}

__global__ void __launch_bounds__(TPB) k_lanczos() {
    __shared__ __align__(16) float sv[N];
    __shared__ float shw[16];
    __shared__ float sred[8];
    __shared__ float sbc[1];

    const int tid = threadIdx.x, bid = blockIdx.x;
    const int q = tid >> 4, lane = tid & 15;
    const int row = bid*16 + q;
    const int myrow = bid*16 + tid;     // valid for tid < 16
    const int warp = tid >> 5, wl = tid & 31;
    unsigned int ep = 0;

    // ---- deterministic start vector (raw); norm partials go to buffer B
    float initx = 0.f;
    if (tid < 16) {
        unsigned int h = (unsigned int)myrow * 2654435761u + 0x9E3779B9u;
        h ^= h>>16; h *= 0x85ebca6bu; h ^= h>>13; h *= 0xc2b2ae35u; h ^= h>>16;
        initx = (float)(h & 0xffffu) * (1.0f/65536.0f) + 0.0625f;
        g_raw[0][myrow] = initx;
    }
    {
        float p = (tid < 16) ? initx*initx : 0.f;
#pragma unroll
        for (int off = 8; off; off >>= 1) p += __shfl_down_sync(0xffffffffu, p, off, 16);
        if (tid == 0) g_partB[bid] = p;
        gbar(ep);
    }
    float nrm = sum_parts(g_partB, sred, sbc);
    float invb_cur = rsqrtf(nrm);
    float invb_prev = 0.f, beta_prev = 0.f;
    int cur = 0;

    for (int j = 0; j < KL; j++) {
        // stage normalized v_j
        for (int i = tid; i < N; i += TPB) sv[i] = __ldcg(&g_raw[cur][i]) * invb_cur;
        __syncthreads();

        // matvec u = M v_j
        const float4* M4  = ((const float4*)g_M) + (size_t)row * (N/4);
        const float4* sv4 = (const float4*)sv;
        float s = 0.f;
#pragma unroll
        for (int t = 0; t < 16; t++) {
            int qi = lane*2 + t*32;
            float4 m0 = M4[qi], m1 = M4[qi+1];
            float4 x0 = sv4[qi], x1 = sv4[qi+1];
            s += m0.x*x0.x + m0.y*x0.y + m0.z*x0.z + m0.w*x0.w
               + m1.x*x1.x + m1.y*x1.y + m1.z*x1.z + m1.w*x1.w;
        }
#pragma unroll
        for (int off = 8; off; off >>= 1) s += __shfl_down_sync(0xffffffffu, s, off, 16);

        // alpha partials -> buffer A  (previous A read was separated by gbar)
        float pa = 0.f;
        if (lane == 0) { shw[q] = s; pa = s * sv[row]; }
#pragma unroll
        for (int off = 16; off; off >>= 1) pa += __shfl_down_sync(0xffffffffu, pa, off);
        if (wl == 0) sred[warp] = pa;
        __syncthreads();
        if (tid == 0) {
            float sa = 0.f;
#pragma unroll
            for (int w = 0; w < 8; w++) sa += sred[w];
            g_partA[bid] = sa;
        }
        gbar(ep);

        float alpha = sum_parts(g_partA, sred, sbc);
        if (bid == 0 && tid == 0) g_alpha[j] = alpha;
        float w = 0.f;
        if (tid < 16) {
            w = shw[tid] - alpha * sv[myrow]
              - beta_prev * invb_prev * g_raw[cur^1][myrow];
            g_raw[cur^1][myrow] = w;
        }
        // beta partials -> buffer B (previous B read separated by the gbar above)
        float pw = (tid < 16) ? w*w : 0.f;
#pragma unroll
        for (int off = 8; off; off >>= 1) pw += __shfl_down_sync(0xffffffffu, pw, off, 16);
        if (tid == 0) g_partB[bid] = pw;
        gbar(ep);

        float b2 = sum_parts(g_partB, sred, sbc);
        float beta = sqrtf(fmaxf(b2, 1e-30f));
        if (bid == 0 && tid == 0) g_betav[j] = beta;
        beta_prev = beta;
        invb_prev = invb_cur;
        invb_cur = 1.0f / beta;
        cur ^= 1;
    }
}

// ------- extremes: double Sturm count, 32-way multisection, 2 warps --------
__global__ void k_extremes(float* out) {
    __shared__ double sa[KL], sb[KL];
    __shared__ double sbounds[2];
    __shared__ double res[2];
    int tid = threadIdx.x;              // 64 threads
    int warp = tid >> 5, lane = tid & 31;

    for (int i = tid; i < KL; i += 64) {
        sa[i] = (double)g_alpha[i];
        sb[i] = (double)g_betav[i];
    }
    __syncthreads();
    if (tid == 0) {
        double lo = 1e300, hi = -1e300;
        for (int i = 0; i < KL; i++) {
            double bl = (i > 0)    ? fabs(sb[i-1]) : 0.0;
            double br = (i < KL-1) ? fabs(sb[i])   : 0.0;
            double a = sa[i];
            if (a - bl - br < lo) lo = a - bl - br;
            if (a + bl + br > hi) hi = a + bl + br;
        }
        sbounds[0] = lo; sbounds[1] = hi;
    }
    __syncthreads();

    int target = (warp == 0) ? KL : 1;  // warp0: lambda_max, warp1: lambda_min
    double lo = sbounds[0], hi = sbounds[1];

    for (int step = 0; step < 7; step++) {
        double w = (hi - lo) * (1.0 / 33.0);
        double x = lo + w * (double)(lane + 1);
        double d = sa[0] - x;
        int cnt = (d < 0.0);
        for (int i = 1; i < KL; i++) {
            double den = d;
            if (fabs(den) < 1e-280) den = (den < 0.0) ? -1e-280 : 1e-280;
            d = (sa[i] - x) - sb[i-1]*sb[i-1] / den;
            cnt += (d < 0.0);
        }
        unsigned mask = __ballot_sync(0xffffffffu, cnt >= target);
        int first = (mask == 0u) ? 32 : (__ffs(mask) - 1);
        if (first < 32) hi = lo + w * (double)(first + 1);
        lo = lo + w * (double)first;
    }
    if (lane == 0) res[warp] = 0.5 * (lo + hi);
    __syncthreads();
    if (tid == 0) {
        double lmax = fmax(res[0], 1e-12);
        double lmin = fmax(res[1], 1e-12);
        out[0] = (float)(log(lmax) - log(lmin));
    }
}

// ---------------- launch ------------------------------------------------------
extern "C" void kernel_launch(void* const* d_in, const int* in_sizes, int n_in,
                              void* d_out, int out_size) {
    const float* pred = (const float*)d_in[0];
    const float* scl  = (const float*)d_in[1];
    const float* Af   = (const float*)d_in[2];
    const int* frows  = (const int*)d_in[3];
    const int* fcols  = (const int*)d_in[4];
    float* out = (float*)d_out;

    k_prep <<<NNZ/TPB, TPB>>>(pred, scl);
    k_count<<<NNZ/TPB, TPB>>>(frows);
    k_scan <<<1, 256>>>();
    k_fill <<<NNZ/TPB, TPB>>>(frows, fcols);

    k_syrk<<<dim3(16,16), 256>>>(Af);

    k_spmm_AC <<<N, TPB>>>();
    k_tr_C_CT <<<dim3(64,64), dim3(32,8)>>>();
    k_spmm_CTG<<<N, TPB>>>();
    k_combine <<<N*N/4/TPB, TPB>>>();
    k_tr_C_G  <<<dim3(64,64), dim3(32,8)>>>();
    k_sym     <<<N*N/4/TPB, TPB>>>();

    k_reset   <<<1, TPB>>>();
    k_lanczos <<<GRID, TPB>>>();
    k_extremes<<<1, 64>>>(out);
}

// round 8
// speedup vs baseline: 7.9183x; 1.0923x over previous
#include <cuda_runtime.h>
#include <math.h>

#define N     2048
#define NNZ   32768
#define KL    96
#define GRID  128
#define TPB   256
#define BK    8

// ---------------- scratch (device globals; no allocation) ------------------
__device__ float g_A[N*N];
__device__ float g_C[N*N];
__device__ float g_CT[N*N];
__device__ float g_G[N*N];
__device__ float g_M[N*N];

__device__ float g_vals[NNZ];
__device__ int   g_rowptr[N+1];
__device__ int   g_cnt[N];
__device__ int   g_colidx[NNZ];
__device__ float g_csrval[NNZ];

__device__ float g_u[2][N];          // raw matvec rows, parity-buffered
__device__ float g_part[2][GRID];    // u.v partials, parity-buffered
__device__ float g_alpha[KL];
__device__ float g_betav[KL];
__device__ volatile unsigned int g_arrive[GRID];
__device__ volatile unsigned int g_release;

// ---------------- CSR build ------------------------------------------------
__global__ void k_prep(const float* __restrict__ pred, const float* __restrict__ scl) {
    int i = blockIdx.x * blockDim.x + threadIdx.x;
    if (i < NNZ) g_vals[i] = pred[i] * scl[i];
    if (i < N)   g_cnt[i] = 0;
    if (blockIdx.x == 0) {
        if (threadIdx.x < GRID) g_arrive[threadIdx.x] = 0;
        if (threadIdx.x == 0)   g_release = 0;
    }
}
__global__ void k_count(const int* __restrict__ rows) {
    int i = blockIdx.x * blockDim.x + threadIdx.x;
    if (i < NNZ) atomicAdd(&g_cnt[rows[i]], 1);
}
__global__ void k_scan() {                     // 256 threads, 8 elems/thread
    int tid = threadIdx.x;
    int lane = tid & 31, warp = tid >> 5;
    int v[8]; int loc = 0;
#pragma unroll
    for (int u = 0; u < 8; u++) { v[u] = g_cnt[tid*8 + u]; loc += v[u]; }
    int sc = loc;
#pragma unroll
    for (int off = 1; off < 32; off <<= 1) {
        int nb = __shfl_up_sync(0xffffffffu, sc, off);
        if (lane >= off) sc += nb;
    }
    __shared__ int wsum[8];
    if (lane == 31) wsum[warp] = sc;
    __syncthreads();
    if (tid == 0) {
        int a = 0;
#pragma unroll
        for (int w = 0; w < 8; w++) { int t = wsum[w]; wsum[w] = a; a += t; }
    }
    __syncthreads();
    int run = sc - loc + wsum[warp];
#pragma unroll
    for (int u = 0; u < 8; u++) {
        g_rowptr[tid*8 + u] = run;
        g_cnt[tid*8 + u]    = run;
        run += v[u];
    }
    if (tid == 255) g_rowptr[N] = run;
}
__global__ void k_fill(const int* __restrict__ rows, const int* __restrict__ cols) {
    int i = blockIdx.x * blockDim.x + threadIdx.x;
    if (i < NNZ) {
        int p = atomicAdd(&g_cnt[rows[i]], 1);
        g_colidx[p] = cols[i];
        g_csrval[p] = g_vals[i];
    }
}

// ---------------- SYRK: A = Af*Af^T / N + I (exactly symmetric) ------------
__global__ void __launch_bounds__(256) k_syrk(const float* __restrict__ Af) {
    int bx = blockIdx.x, by = blockIdx.y;
    if (bx < by) return;
    __shared__ __align__(16) float As[BK][132];
    __shared__ __align__(16) float Bs[BK][132];
    int tid = threadIdx.x;
    int tx = tid & 15, ty = tid >> 4;
    int row0 = by * 128, col0 = bx * 128;

    float acc[8][8];
#pragma unroll
    for (int i = 0; i < 8; i++)
#pragma unroll
        for (int j = 0; j < 8; j++) acc[i][j] = 0.f;

    int lr = tid >> 1;
    int lk = (tid & 1) * 4;
    const float* abase = Af + (size_t)(row0 + lr) * N + lk;
    const float* bbase = Af + (size_t)(col0 + lr) * N + lk;
    float4 pa = *(const float4*)abase;
    float4 pb = *(const float4*)bbase;

    for (int kk = 0; kk < N; kk += BK) {
        __syncthreads();
        As[lk+0][lr]=pa.x; As[lk+1][lr]=pa.y; As[lk+2][lr]=pa.z; As[lk+3][lr]=pa.w;
        Bs[lk+0][lr]=pb.x; Bs[lk+1][lr]=pb.y; Bs[lk+2][lr]=pb.z; Bs[lk+3][lr]=pb.w;
        __syncthreads();
        if (kk + BK < N) {
            pa = *(const float4*)(abase + kk + BK);
            pb = *(const float4*)(bbase + kk + BK);
        }
#pragma unroll
        for (int k = 0; k < BK; k++) {
            float4 a0 = *(const float4*)&As[k][4*ty];
            float4 a1 = *(const float4*)&As[k][64+4*ty];
            float4 b0 = *(const float4*)&Bs[k][4*tx];
            float4 b1 = *(const float4*)&Bs[k][64+4*tx];
            float av[8] = {a0.x,a0.y,a0.z,a0.w,a1.x,a1.y,a1.z,a1.w};
            float bv[8] = {b0.x,b0.y,b0.z,b0.w,b1.x,b1.y,b1.z,b1.w};
#pragma unroll
            for (int i = 0; i < 8; i++)
#pragma unroll
                for (int j = 0; j < 8; j++) acc[i][j] += av[i]*bv[j];
        }
    }
    float invn = 1.0f / (float)N;
#pragma unroll
    for (int i = 0; i < 8; i++) {
        int gi = row0 + ((i<4) ? (4*ty+i) : (64+4*ty+i-4));
#pragma unroll
        for (int j = 0; j < 8; j++) {
            int gj = col0 + ((j<4) ? (4*tx+j) : (64+4*tx+j-4));
            float val = acc[i][j]*invn + ((gi==gj)?1.0f:0.0f);
            g_A[(size_t)gi*N+gj] = val;
            if (bx > by) g_A[(size_t)gj*N+gi] = val;
        }
    }
}

// ---------------- SpMM: Y = S * X -------------------------------------------
__device__ __forceinline__ void spmm_body(const float* __restrict__ X, float* __restrict__ Y) {
    int r = blockIdx.x, t = threadIdx.x;
    int s = g_rowptr[r], e = g_rowptr[r+1];
    float acc[8] = {0,0,0,0,0,0,0,0};
    for (int k = s; k < e; k++) {
        int c = g_colidx[k];
        float v = g_csrval[k];
        const float* xr = X + (size_t)c * N;
#pragma unroll
        for (int u = 0; u < 8; u++) acc[u] += v * xr[t + u*TPB];
    }
    float* yr = Y + (size_t)r * N;
#pragma unroll
    for (int u = 0; u < 8; u++) yr[t + u*TPB] = acc[u];
}
__global__ void k_spmm_AC()  { spmm_body(g_A,  g_C); }
__global__ void k_spmm_CTG() { spmm_body(g_CT, g_G); }

// ---------------- transpose --------------------------------------------------
__device__ __forceinline__ void tr_body(const float* __restrict__ in, float* __restrict__ out) {
    __shared__ float t[32][33];
    int bx = blockIdx.x*32, by = blockIdx.y*32;
    int x = bx + threadIdx.x;
#pragma unroll
    for (int j = 0; j < 32; j += 8)
        t[threadIdx.y+j][threadIdx.x] = in[(size_t)(by+threadIdx.y+j)*N + x];
    __syncthreads();
    int x2 = by + threadIdx.x;
#pragma unroll
    for (int j = 0; j < 32; j += 8)
        out[(size_t)(bx+threadIdx.y+j)*N + x2] = t[threadIdx.x][threadIdx.y+j];
}
__global__ void k_tr_C_CT() { tr_body(g_C, g_CT); }
__global__ void k_tr_C_G()  { tr_body(g_C, g_G); }

// ---------------- elementwise ------------------------------------------------
__global__ void k_combine() {   // g_C = A + C + C^T + G
    int i = blockIdx.x*blockDim.x + threadIdx.x;
    float4 a = ((const float4*)g_A)[i];
    float4 c = ((const float4*)g_C)[i];
    float4 t = ((const float4*)g_CT)[i];
    float4 g = ((const float4*)g_G)[i];
    float4 r; r.x=a.x+c.x+t.x+g.x; r.y=a.y+c.y+t.y+g.y;
    r.z=a.z+c.z+t.z+g.z; r.w=a.w+c.w+t.w+g.w;
    ((float4*)g_C)[i] = r;
}
__global__ void k_sym() {       // g_M = 0.5*(C + C^T)
    int i = blockIdx.x*blockDim.x + threadIdx.x;
    float4 c = ((const float4*)g_C)[i];
    float4 g = ((const float4*)g_G)[i];
    float4 r; r.x=0.5f*(c.x+g.x); r.y=0.5f*(c.y+g.y);
    r.z=0.5f*(c.z+g.z); r.w=0.5f*(c.w+g.w);
    ((float4*)g_M)[i] = r;
}

// ---------------- Lanczos: persistent, 1 barrier/iter, local beta ----------
__device__ __forceinline__ void gbar(unsigned int& ep) {
    ep++;
    __threadfence();
    __syncthreads();
    if (blockIdx.x == 0) {
        if (threadIdx.x > 0 && threadIdx.x < GRID) {
            while (g_arrive[threadIdx.x] < ep) __nanosleep(20);
        }
        __syncthreads();
        if (threadIdx.x == 0) g_release = ep;
    } else {
        if (threadIdx.x == 0) {
            g_arrive[blockIdx.x] = ep;
            while (g_release < ep) __nanosleep(20);
        }
    }
    __syncthreads();
    __threadfence();
}

// sum 128 float partials (identical result in every block)
__device__ __forceinline__ float sum_parts(const float* part, float* sred, float* sbc) {
    int tid = threadIdx.x, warp = tid >> 5, wl = tid & 31;
    float a = (tid < GRID) ? __ldcg(&part[tid]) : 0.f;
#pragma unroll
    for (int off = 16; off; off >>= 1) a += __shfl_down_sync(0xffffffffu, a, off);
    if (wl == 0) sred[warp] = a;
    __syncthreads();
    if (tid == 0) {
        float s = 0.f;
#pragma unroll
        for (int w = 0; w < 4; w++) s += sred[w];
        sbc[0] = s;
    }
    __syncthreads();
    return sbc[0];
}

// deterministic block-local sum of TPB per-thread values (same order every block)
__device__ __forceinline__ float block_sum(float p, float* sred, float* sbc) {
    int tid = threadIdx.x, warp = tid >> 5, wl = tid & 31;
#pragma unroll
    for (int off = 16; off; off >>= 1) p += __shfl_down_sync(0xffffffffu, p, off);
    if (wl == 0) sred[warp] = p;
    __syncthreads();
    if (tid == 0) {
        float s = 0.f;
#pragma unroll
        for (int w = 0; w < 8; w++) s += sred[w];
        sbc[0] = s;
    }
    __syncthreads();
    return sbc[0];
}

__global__ void __launch_bounds__(TPB) k_lanczos() {
    __shared__ __align__(16) float svbuf[2][N];     // v_j and v_{j-1}
    __shared__ float shw[16];
    __shared__ float sred[8];
    __shared__ float sbc[1];

    const int tid = threadIdx.x, bid = blockIdx.x;
    const int q = tid >> 4, lane = tid & 15;
    const int row = bid*16 + q;
    const int myrow = bid*16 + tid;     // valid for tid < 16
    unsigned int ep = 0;

    // ---- init: publish raw start rows, one barrier, then local norm ----
    if (tid < 16) {
        unsigned int h = (unsigned int)myrow * 2654435761u + 0x9E3779B9u;
        h ^= h>>16; h *= 0x85ebca6bu; h ^= h>>13; h *= 0xc2b2ae35u; h ^= h>>16;
        g_u[1][myrow] = (float)(h & 0xffffu) * (1.0f/65536.0f) + 0.0625f;
    }
    gbar(ep);

    float* svc = svbuf[0];
    float* svp = svbuf[1];
    {
        float p = 0.f;
        for (int i = tid; i < N; i += TPB) {
            float x = __ldcg(&g_u[1][i]);
            svc[i] = x;                 // temporarily raw
            svp[i] = 0.f;
            p += x * x;
        }
        float n0 = block_sum(p, sred, sbc);   // identical in every block
        float inv0 = rsqrtf(n0);
        for (int i = tid; i < N; i += TPB) svc[i] *= inv0;
        __syncthreads();
    }
    float beta_p = 0.f;

    for (int j = 0; j < KL; j++) {
        const int b = j & 1;
        // ---- matvec u = M v_j (16 rows/block, 16 lanes/row)
        const float4* M4  = ((const float4*)g_M) + (size_t)row * (N/4);
        const float4* sv4 = (const float4*)svc;
        float s = 0.f;
#pragma unroll
        for (int t = 0; t < 16; t++) {
            int qi = lane*2 + t*32;
            float4 m0 = M4[qi], m1 = M4[qi+1];
            float4 x0 = sv4[qi], x1 = sv4[qi+1];
            s += m0.x*x0.x + m0.y*x0.y + m0.z*x0.z + m0.w*x0.w
               + m1.x*x1.x + m1.y*x1.y + m1.z*x1.z + m1.w*x1.w;
        }
#pragma unroll
        for (int off = 8; off; off >>= 1) s += __shfl_down_sync(0xffffffffu, s, off, 16);
        if (lane == 0) shw[q] = s;
        __syncthreads();

        // ---- publish raw u rows + partial u.v; ONE barrier
        float pa = 0.f;
        if (tid < 16) {
            float uval = shw[tid];
            g_u[b][myrow] = uval;
            pa = uval * svc[myrow];
        }
#pragma unroll
        for (int off = 8; off; off >>= 1) pa += __shfl_down_sync(0xffffffffu, pa, off, 16);
        if (tid == 0) g_part[b][bid] = pa;
        gbar(ep);

        // ---- alpha (global), then w and beta computed LOCALLY (full vector)
        float alpha = sum_parts(g_part[b], sred, sbc);
        float pw = 0.f;
        for (int i = tid; i < N; i += TPB) {
            float w = __ldcg(&g_u[b][i]) - alpha*svc[i] - beta_p*svp[i];
            svp[i] = w;                 // svp becomes raw w
            pw += w * w;
        }
        float nw = block_sum(pw, sred, sbc);     // identical in every block
        float beta = sqrtf(fmaxf(nw, 1e-30f));
        if (bid == 0 && tid == 0) { g_alpha[j] = alpha; g_betav[j] = beta; }
        float invb = 1.0f / beta;
        for (int i = tid; i < N; i += TPB) svp[i] *= invb;
        __syncthreads();
        float* t = svc; svc = svp; svp = t;
        beta_p = beta;
    }
}

// ------- extremes: double Sturm count, 32-way multisection, 2 warps --------
__global__ void k_extremes(float* out) {
    __shared__ double sa[KL], sb[KL];
    __shared__ double sbounds[2];
    __shared__ double res[2];
    int tid = threadIdx.x;              // 64 threads
    int warp = tid >> 5, lane = tid & 31;

    for (int i = tid; i < KL; i += 64) {
        sa[i] = (double)g_alpha[i];
        sb[i] = (double)g_betav[i];
    }
    __syncthreads();
    if (tid == 0) {
        double lo = 1e300, hi = -1e300;
        for (int i = 0; i < KL; i++) {
            double bl = (i > 0)    ? fabs(sb[i-1]) : 0.0;
            double br = (i < KL-1) ? fabs(sb[i])   : 0.0;
            double a = sa[i];
            if (a - bl - br < lo) lo = a - bl - br;
            if (a + bl + br > hi) hi = a + bl + br;
        }
        sbounds[0] = lo; sbounds[1] = hi;
    }
    __syncthreads();

    int target = (warp == 0) ? KL : 1;  // warp0: lambda_max, warp1: lambda_min
    double lo = sbounds[0], hi = sbounds[1];

    for (int step = 0; step < 7; step++) {
        double w = (hi - lo) * (1.0 / 33.0);
        double x = lo + w * (double)(lane + 1);
        double d = sa[0] - x;
        int cnt = (d < 0.0);
        for (int i = 1; i < KL; i++) {
            double den = d;
            if (fabs(den) < 1e-280) den = (den < 0.0) ? -1e-280 : 1e-280;
            d = (sa[i] - x) - sb[i-1]*sb[i-1] / den;
            cnt += (d < 0.0);
        }
        unsigned mask = __ballot_sync(0xffffffffu, cnt >= target);
        int first = (mask == 0u) ? 32 : (__ffs(mask) - 1);
        if (first < 32) hi = lo + w * (double)(first + 1);
        lo = lo + w * (double)first;
    }
    if (lane == 0) res[warp] = 0.5 * (lo + hi);
    __syncthreads();
    if (tid == 0) {
        double lmax = fmax(res[0], 1e-12);
        double lmin = fmax(res[1], 1e-12);
        out[0] = (float)(log(lmax) - log(lmin));
    }
}

// ---------------- launch ------------------------------------------------------
extern "C" void kernel_launch(void* const* d_in, const int* in_sizes, int n_in,
                              void* d_out, int out_size) {
    const float* pred = (const float*)d_in[0];
    const float* scl  = (const float*)d_in[1];
    const float* Af   = (const float*)d_in[2];
    const int* frows  = (const int*)d_in[3];
    const int* fcols  = (const int*)d_in[4];
    float* out = (float*)d_out;

    k_prep <<<NNZ/TPB, TPB>>>(pred, scl);
    k_count<<<NNZ/TPB, TPB>>>(frows);
    k_scan <<<1, 256>>>();
    k_fill <<<NNZ/TPB, TPB>>>(frows, fcols);

    k_syrk<<<dim3(16,16), 256>>>(Af);

    k_spmm_AC <<<N, TPB>>>();
    k_tr_C_CT <<<dim3(64,64), dim3(32,8)>>>();
    k_spmm_CTG<<<N, TPB>>>();
    k_combine <<<N*N/4/TPB, TPB>>>();
    k_tr_C_G  <<<dim3(64,64), dim3(32,8)>>>();
    k_sym     <<<N*N/4/TPB, TPB>>>();

    k_lanczos <<<GRID, TPB>>>();
    k_extremes<<<1, 64>>>(out);
}

// round 9
// speedup vs baseline: 10.4370x; 1.3181x over previous
#include <cuda_runtime.h>
#include <math.h>

#define N     2048
#define NNZ   32768
#define KL    64
#define GRID  128
#define TPB   256
#define BK    8

// ---------------- scratch (device globals; no allocation) ------------------
__device__ float g_A[N*N];
__device__ float g_C[N*N];
__device__ float g_CT[N*N];
__device__ float g_M[N*N];

__device__ float g_vals[NNZ];
__device__ int   g_rowptr[N+1];
__device__ int   g_cnt[N];
__device__ int   g_colidx[NNZ];
__device__ float g_csrval[NNZ];

__device__ float g_u[2][N];          // raw matvec rows, parity-buffered
__device__ float g_part[2][GRID];    // u.v partials, parity-buffered
__device__ float g_alpha[KL];
__device__ float g_betav[KL];
__device__ volatile unsigned int g_arrive[GRID];
__device__ volatile unsigned int g_release;

// ---------------- CSR build ------------------------------------------------
__global__ void k_prep(const float* __restrict__ pred, const float* __restrict__ scl) {
    int i = blockIdx.x * blockDim.x + threadIdx.x;
    if (i < NNZ) g_vals[i] = pred[i] * scl[i];
    if (i < N)   g_cnt[i] = 0;
    if (blockIdx.x == 0) {
        if (threadIdx.x < GRID) g_arrive[threadIdx.x] = 0;
        if (threadIdx.x == 0)   g_release = 0;
    }
}
__global__ void k_count(const int* __restrict__ rows) {
    int i = blockIdx.x * blockDim.x + threadIdx.x;
    if (i < NNZ) atomicAdd(&g_cnt[rows[i]], 1);
}
__global__ void k_scan() {                     // 256 threads, 8 elems/thread
    int tid = threadIdx.x;
    int lane = tid & 31, warp = tid >> 5;
    int v[8]; int loc = 0;
#pragma unroll
    for (int u = 0; u < 8; u++) { v[u] = g_cnt[tid*8 + u]; loc += v[u]; }
    int sc = loc;
#pragma unroll
    for (int off = 1; off < 32; off <<= 1) {
        int nb = __shfl_up_sync(0xffffffffu, sc, off);
        if (lane >= off) sc += nb;
    }
    __shared__ int wsum[8];
    if (lane == 31) wsum[warp] = sc;
    __syncthreads();
    if (tid == 0) {
        int a = 0;
#pragma unroll
        for (int w = 0; w < 8; w++) { int t = wsum[w]; wsum[w] = a; a += t; }
    }
    __syncthreads();
    int run = sc - loc + wsum[warp];
#pragma unroll
    for (int u = 0; u < 8; u++) {
        g_rowptr[tid*8 + u] = run;
        g_cnt[tid*8 + u]    = run;
        run += v[u];
    }
    if (tid == 255) g_rowptr[N] = run;
}
__global__ void k_fill(const int* __restrict__ rows, const int* __restrict__ cols) {
    int i = blockIdx.x * blockDim.x + threadIdx.x;
    if (i < NNZ) {
        int p = atomicAdd(&g_cnt[rows[i]], 1);
        g_colidx[p] = cols[i];
        g_csrval[p] = g_vals[i];
    }
}

// ---------------- SYRK: A = Af*Af^T / N + I (exactly symmetric) ------------
__global__ void __launch_bounds__(256) k_syrk(const float* __restrict__ Af) {
    int bx = blockIdx.x, by = blockIdx.y;
    if (bx < by) return;
    __shared__ __align__(16) float As[BK][132];
    __shared__ __align__(16) float Bs[BK][132];
    int tid = threadIdx.x;
    int tx = tid & 15, ty = tid >> 4;
    int row0 = by * 128, col0 = bx * 128;

    float acc[8][8];
#pragma unroll
    for (int i = 0; i < 8; i++)
#pragma unroll
        for (int j = 0; j < 8; j++) acc[i][j] = 0.f;

    int lr = tid >> 1;
    int lk = (tid & 1) * 4;
    const float* abase = Af + (size_t)(row0 + lr) * N + lk;
    const float* bbase = Af + (size_t)(col0 + lr) * N + lk;
    float4 pa = *(const float4*)abase;
    float4 pb = *(const float4*)bbase;

    for (int kk = 0; kk < N; kk += BK) {
        __syncthreads();
        As[lk+0][lr]=pa.x; As[lk+1][lr]=pa.y; As[lk+2][lr]=pa.z; As[lk+3][lr]=pa.w;
        Bs[lk+0][lr]=pb.x; Bs[lk+1][lr]=pb.y; Bs[lk+2][lr]=pb.z; Bs[lk+3][lr]=pb.w;
        __syncthreads();
        if (kk + BK < N) {
            pa = *(const float4*)(abase + kk + BK);
            pb = *(const float4*)(bbase + kk + BK);
        }
#pragma unroll
        for (int k = 0; k < BK; k++) {
            float4 a0 = *(const float4*)&As[k][4*ty];
            float4 a1 = *(const float4*)&As[k][64+4*ty];
            float4 b0 = *(const float4*)&Bs[k][4*tx];
            float4 b1 = *(const float4*)&Bs[k][64+4*tx];
            float av[8] = {a0.x,a0.y,a0.z,a0.w,a1.x,a1.y,a1.z,a1.w};
            float bv[8] = {b0.x,b0.y,b0.z,b0.w,b1.x,b1.y,b1.z,b1.w};
#pragma unroll
            for (int i = 0; i < 8; i++)
#pragma unroll
                for (int j = 0; j < 8; j++) acc[i][j] += av[i]*bv[j];
        }
    }
    float invn = 1.0f / (float)N;
#pragma unroll
    for (int i = 0; i < 8; i++) {
        int gi = row0 + ((i<4) ? (4*ty+i) : (64+4*ty+i-4));
#pragma unroll
        for (int j = 0; j < 8; j++) {
            int gj = col0 + ((j<4) ? (4*tx+j) : (64+4*tx+j-4));
            float val = acc[i][j]*invn + ((gi==gj)?1.0f:0.0f);
            g_A[(size_t)gi*N+gj] = val;
            if (bx > by) g_A[(size_t)gj*N+gi] = val;
        }
    }
}

// ---------------- SpMM 1: C = S * A ------------------------------------------
__global__ void k_spmm_AC() {
    int r = blockIdx.x, t = threadIdx.x;
    int s = g_rowptr[r], e = g_rowptr[r+1];
    float acc[8] = {0,0,0,0,0,0,0,0};
    for (int k = s; k < e; k++) {
        int c = g_colidx[k];
        float v = g_csrval[k];
        const float* xr = g_A + (size_t)c * N;
#pragma unroll
        for (int u = 0; u < 8; u++) acc[u] += v * xr[t + u*TPB];
    }
    float* yr = g_C + (size_t)r * N;
#pragma unroll
    for (int u = 0; u < 8; u++) yr[t + u*TPB] = acc[u];
}

// ---------------- transpose: CT = C^T ----------------------------------------
__global__ void k_tr_C_CT() {
    __shared__ float t[32][33];
    int bx = blockIdx.x*32, by = blockIdx.y*32;
    int x = bx + threadIdx.x;
#pragma unroll
    for (int j = 0; j < 32; j += 8)
        t[threadIdx.y+j][threadIdx.x] = g_C[(size_t)(by+threadIdx.y+j)*N + x];
    __syncthreads();
    int x2 = by + threadIdx.x;
#pragma unroll
    for (int j = 0; j < 32; j += 8)
        g_CT[(size_t)(bx+threadIdx.y+j)*N + x2] = t[threadIdx.x][threadIdx.y+j];
}

// ------- SpMM 2 fused: M = A + C + C^T + S*C^T (exact-symmetric combo) ------
__global__ void k_spmm_M() {
    int r = blockIdx.x, t = threadIdx.x;
    int s = g_rowptr[r], e = g_rowptr[r+1];
    float acc[8] = {0,0,0,0,0,0,0,0};
    for (int k = s; k < e; k++) {
        int c = g_colidx[k];
        float v = g_csrval[k];
        const float* xr = g_CT + (size_t)c * N;
#pragma unroll
        for (int u = 0; u < 8; u++) acc[u] += v * xr[t + u*TPB];
    }
    const float* ar = g_A  + (size_t)r * N;
    const float* cr = g_C  + (size_t)r * N;
    const float* tr = g_CT + (size_t)r * N;
    float* mr = g_M + (size_t)r * N;
#pragma unroll
    for (int u = 0; u < 8; u++) {
        int i = t + u*TPB;
        mr[i] = ar[i] + cr[i] + tr[i] + acc[u];
    }
}

// ---------------- Lanczos: persistent, 1 barrier/iter, local beta ----------
__device__ __forceinline__ void gbar(unsigned int& ep) {
    ep++;
    __threadfence();
    __syncthreads();
    if (blockIdx.x == 0) {
        if (threadIdx.x > 0 && threadIdx.x < GRID) {
            while (g_arrive[threadIdx.x] < ep) __nanosleep(20);
        }
        __syncthreads();
        if (threadIdx.x == 0) g_release = ep;
    } else {
        if (threadIdx.x == 0) {
            g_arrive[blockIdx.x] = ep;
            while (g_release < ep) __nanosleep(20);
        }
    }
    __syncthreads();
    __threadfence();
}

// sum 128 float partials (identical result in every block)
__device__ __forceinline__ float sum_parts(const float* part, float* sred, float* sbc) {
    int tid = threadIdx.x, warp = tid >> 5, wl = tid & 31;
    float a = (tid < GRID) ? __ldcg(&part[tid]) : 0.f;
#pragma unroll
    for (int off = 16; off; off >>= 1) a += __shfl_down_sync(0xffffffffu, a, off);
    if (wl == 0) sred[warp] = a;
    __syncthreads();
    if (tid == 0) {
        float s = 0.f;
#pragma unroll
        for (int w = 0; w < 4; w++) s += sred[w];
        sbc[0] = s;
    }
    __syncthreads();
    return sbc[0];
}

// deterministic block-local sum of TPB per-thread values (same order every block)
__device__ __forceinline__ float block_sum(float p, float* sred, float* sbc) {
    int tid = threadIdx.x, warp = tid >> 5, wl = tid & 31;
#pragma unroll
    for (int off = 16; off; off >>= 1) p += __shfl_down_sync(0xffffffffu, p, off);
    if (wl == 0) sred[warp] = p;
    __syncthreads();
    if (tid == 0) {
        float s = 0.f;
#pragma unroll
        for (int w = 0; w < 8; w++) s += sred[w];
        sbc[0] = s;
    }
    __syncthreads();
    return sbc[0];
}

__global__ void __launch_bounds__(TPB) k_lanczos() {
    __shared__ __align__(16) float svbuf[2][N];     // v_j and v_{j-1}
    __shared__ float shw[16];
    __shared__ float sred[8];
    __shared__ float sbc[1];

    const int tid = threadIdx.x, bid = blockIdx.x;
    const int q = tid >> 4, lane = tid & 15;
    const int row = bid*16 + q;
    const int myrow = bid*16 + tid;     // valid for tid < 16
    unsigned int ep = 0;

    // ---- init: publish raw start rows, one barrier, then local norm ----
    if (tid < 16) {
        unsigned int h = (unsigned int)myrow * 2654435761u + 0x9E3779B9u;
        h ^= h>>16; h *= 0x85ebca6bu; h ^= h>>13; h *= 0xc2b2ae35u; h ^= h>>16;
        g_u[1][myrow] = (float)(h & 0xffffu) * (1.0f/65536.0f) + 0.0625f;
    }
    gbar(ep);

    float* svc = svbuf[0];
    float* svp = svbuf[1];
    {
        float p = 0.f;
        for (int i = tid; i < N; i += TPB) {
            float x = __ldcg(&g_u[1][i]);
            svc[i] = x;                 // temporarily raw
            svp[i] = 0.f;
            p += x * x;
        }
        float n0 = block_sum(p, sred, sbc);   // identical in every block
        float inv0 = rsqrtf(n0);
        for (int i = tid; i < N; i += TPB) svc[i] *= inv0;
        __syncthreads();
    }
    float beta_p = 0.f;

    for (int j = 0; j < KL; j++) {
        const int b = j & 1;
        // ---- matvec u = M v_j (16 rows/block, 16 lanes/row)
        const float4* M4  = ((const float4*)g_M) + (size_t)row * (N/4);
        const float4* sv4 = (const float4*)svc;
        float s = 0.f;
#pragma unroll
        for (int t = 0; t < 16; t++) {
            int qi = lane*2 + t*32;
            float4 m0 = M4[qi], m1 = M4[qi+1];
            float4 x0 = sv4[qi], x1 = sv4[qi+1];
            s += m0.x*x0.x + m0.y*x0.y + m0.z*x0.z + m0.w*x0.w
               + m1.x*x1.x + m1.y*x1.y + m1.z*x1.z + m1.w*x1.w;
        }
#pragma unroll
        for (int off = 8; off; off >>= 1) s += __shfl_down_sync(0xffffffffu, s, off, 16);
        if (lane == 0) shw[q] = s;
        __syncthreads();

        // ---- publish raw u rows + partial u.v; ONE barrier
        float pa = 0.f;
        if (tid < 16) {
            float uval = shw[tid];
            g_u[b][myrow] = uval;
            pa = uval * svc[myrow];
        }
#pragma unroll
        for (int off = 8; off; off >>= 1) pa += __shfl_down_sync(0xffffffffu, pa, off, 16);
        if (tid == 0) g_part[b][bid] = pa;
        gbar(ep);

        // ---- alpha (global), then w and beta computed LOCALLY (full vector)
        float alpha = sum_parts(g_part[b], sred, sbc);
        float pw = 0.f;
        for (int i = tid; i < N; i += TPB) {
            float w = __ldcg(&g_u[b][i]) - alpha*svc[i] - beta_p*svp[i];
            svp[i] = w;                 // svp becomes raw w
            pw += w * w;
        }
        float nw = block_sum(pw, sred, sbc);     // identical in every block
        float beta = sqrtf(fmaxf(nw, 1e-30f));
        if (bid == 0 && tid == 0) { g_alpha[j] = alpha; g_betav[j] = beta; }
        float invb = 1.0f / beta;
        for (int i = tid; i < N; i += TPB) svp[i] *= invb;
        __syncthreads();
        float* t = svc; svc = svp; svp = t;
        beta_p = beta;
    }
}

// ------- extremes: double Sturm count, 32-way multisection, 2 warps --------
__global__ void k_extremes(float* out) {
    __shared__ double sa[KL], sb[KL];
    __shared__ double sbounds[2];
    __shared__ double res[2];
    int tid = threadIdx.x;              // 64 threads
    int warp = tid >> 5, lane = tid & 31;

    for (int i = tid; i < KL; i += 64) {
        sa[i] = (double)g_alpha[i];
        sb[i] = (double)g_betav[i];
    }
    __syncthreads();
    if (tid == 0) {
        double lo = 1e300, hi = -1e300;
        for (int i = 0; i < KL; i++) {
            double bl = (i > 0)    ? fabs(sb[i-1]) : 0.0;
            double br = (i < KL-1) ? fabs(sb[i])   : 0.0;
            double a = sa[i];
            if (a - bl - br < lo) lo = a - bl - br;
            if (a + bl + br > hi) hi = a + bl + br;
        }
        sbounds[0] = lo; sbounds[1] = hi;
    }
    __syncthreads();

    int target = (warp == 0) ? KL : 1;  // warp0: lambda_max, warp1: lambda_min
    double lo = sbounds[0], hi = sbounds[1];

    for (int step = 0; step < 7; step++) {
        double w = (hi - lo) * (1.0 / 33.0);
        double x = lo + w * (double)(lane + 1);
        double d = sa[0] - x;
        int cnt = (d < 0.0);
        for (int i = 1; i < KL; i++) {
            double den = d;
            if (fabs(den) < 1e-280) den = (den < 0.0) ? -1e-280 : 1e-280;
            d = (sa[i] - x) - sb[i-1]*sb[i-1] / den;
            cnt += (d < 0.0);
        }
        unsigned mask = __ballot_sync(0xffffffffu, cnt >= target);
        int first = (mask == 0u) ? 32 : (__ffs(mask) - 1);
        if (first < 32) hi = lo + w * (double)(first + 1);
        lo = lo + w * (double)first;
    }
    if (lane == 0) res[warp] = 0.5 * (lo + hi);
    __syncthreads();
    if (tid == 0) {
        double lmax = fmax(res[0], 1e-12);
        double lmin = fmax(res[1], 1e-12);
        out[0] = (float)(log(lmax) - log(lmin));
    }
}

// ---------------- launch ------------------------------------------------------
extern "C" void kernel_launch(void* const* d_in, const int* in_sizes, int n_in,
                              void* d_out, int out_size) {
    const float* pred = (const float*)d_in[0];
    const float* scl  = (const float*)d_in[1];
    const float* Af   = (const float*)d_in[2];
    const int* frows  = (const int*)d_in[3];
    const int* fcols  = (const int*)d_in[4];
    float* out = (float*)d_out;

    k_prep <<<NNZ/TPB, TPB>>>(pred, scl);
    k_count<<<NNZ/TPB, TPB>>>(frows);
    k_scan <<<1, 256>>>();
    k_fill <<<NNZ/TPB, TPB>>>(frows, fcols);

    k_syrk<<<dim3(16,16), 256>>>(Af);

    k_spmm_AC <<<N, TPB>>>();
    k_tr_C_CT <<<dim3(64,64), dim3(32,8)>>>();
    k_spmm_M  <<<N, TPB>>>();

    k_lanczos <<<GRID, TPB>>>();
    k_extremes<<<1, 64>>>(out);
}

// round 11
// speedup vs baseline: 10.4894x; 1.0050x over previous
#include <cuda_runtime.h>
#include <cstdint>
#include <math.h>

#define N     2048
#define NNZ   32768
#define KL    64
#define GRID  128
#define TPB   256
#define BK    8

// ---------------- scratch (device globals; no allocation) ------------------
__device__ float g_A[N*N];
__device__ float g_C[N*N];
__device__ float g_CT[N*N];
__device__ float g_M[N*N];

__device__ float g_vals[NNZ];
__device__ int   g_rowptr[N+1];
__device__ int   g_cnt[N];
__device__ int   g_colidx[NNZ];
__device__ float g_csrval[NNZ];

__device__ float g_u[2][N];
__device__ float g_part[2][GRID];
__device__ float g_alpha[KL];
__device__ float g_betav[KL];
__device__ volatile unsigned int g_arrive[GRID];
__device__ volatile unsigned int g_release;

// ---------------- CSR build ------------------------------------------------
__global__ void k_prep(const float* __restrict__ pred, const float* __restrict__ scl) {
    int i = blockIdx.x * blockDim.x + threadIdx.x;
    if (i < NNZ) g_vals[i] = pred[i] * scl[i];
    if (i < N)   g_cnt[i] = 0;
    if (blockIdx.x == 0) {
        if (threadIdx.x < GRID) g_arrive[threadIdx.x] = 0;
        if (threadIdx.x == 0)   g_release = 0;
    }
}
__global__ void k_count(const int* __restrict__ rows) {
    int i = blockIdx.x * blockDim.x + threadIdx.x;
    if (i < NNZ) atomicAdd(&g_cnt[rows[i]], 1);
}
__global__ void k_scan() {
    int tid = threadIdx.x;
    int lane = tid & 31, warp = tid >> 5;
    int v[8]; int loc = 0;
#pragma unroll
    for (int u = 0; u < 8; u++) { v[u] = g_cnt[tid*8 + u]; loc += v[u]; }
    int sc = loc;
#pragma unroll
    for (int off = 1; off < 32; off <<= 1) {
        int nb = __shfl_up_sync(0xffffffffu, sc, off);
        if (lane >= off) sc += nb;
    }
    __shared__ int wsum[8];
    if (lane == 31) wsum[warp] = sc;
    __syncthreads();
    if (tid == 0) {
        int a = 0;
#pragma unroll
        for (int w = 0; w < 8; w++) { int t = wsum[w]; wsum[w] = a; a += t; }
    }
    __syncthreads();
    int run = sc - loc + wsum[warp];
#pragma unroll
    for (int u = 0; u < 8; u++) {
        g_rowptr[tid*8 + u] = run;
        g_cnt[tid*8 + u]    = run;
        run += v[u];
    }
    if (tid == 255) g_rowptr[N] = run;
}
__global__ void k_fill(const int* __restrict__ rows, const int* __restrict__ cols) {
    int i = blockIdx.x * blockDim.x + threadIdx.x;
    if (i < NNZ) {
        int p = atomicAdd(&g_cnt[rows[i]], 1);
        g_colidx[p] = cols[i];
        g_csrval[p] = g_vals[i];
    }
}

// ------ SYRK: A = Af*Af^T / N + I  (packed f32x2 FFMA2 inner loop) ---------
__global__ void __launch_bounds__(256) k_syrk(const float* __restrict__ Af) {
    int bx = blockIdx.x, by = blockIdx.y;
    if (bx < by) return;
    __shared__ __align__(16) float As[BK][132];
    __shared__ __align__(16) float Bs[BK][132];
    int tid = threadIdx.x;
    int tx = tid & 15, ty = tid >> 4;
    int row0 = by * 128, col0 = bx * 128;

    // packed accumulators: acc2[i][jj] = (acc[i][2jj], acc[i][2jj+1])
    uint64_t acc2[8][4];
#pragma unroll
    for (int i = 0; i < 8; i++)
#pragma unroll
        for (int j = 0; j < 4; j++) acc2[i][j] = 0ull;

    int lr = tid >> 1;
    int lk = (tid & 1) * 4;
    const float* abase = Af + (size_t)(row0 + lr) * N + lk;
    const float* bbase = Af + (size_t)(col0 + lr) * N + lk;
    float4 pa = *(const float4*)abase;
    float4 pb = *(const float4*)bbase;

    for (int kk = 0; kk < N; kk += BK) {
        __syncthreads();
        As[lk+0][lr]=pa.x; As[lk+1][lr]=pa.y; As[lk+2][lr]=pa.z; As[lk+3][lr]=pa.w;
        Bs[lk+0][lr]=pb.x; Bs[lk+1][lr]=pb.y; Bs[lk+2][lr]=pb.z; Bs[lk+3][lr]=pb.w;
        __syncthreads();
        if (kk + BK < N) {
            pa = *(const float4*)(abase + kk + BK);
            pb = *(const float4*)(bbase + kk + BK);
        }
#pragma unroll
        for (int k = 0; k < BK; k++) {
            float4 a0 = *(const float4*)&As[k][4*ty];
            float4 a1 = *(const float4*)&As[k][64+4*ty];
            // b as packed 64-bit pairs straight out of shared (16B-aligned)
            const uint64_t* bq0 = (const uint64_t*)&Bs[k][4*tx];
            const uint64_t* bq1 = (const uint64_t*)&Bs[k][64+4*tx];
            uint64_t bp0 = bq0[0], bp1 = bq0[1], bp2 = bq1[0], bp3 = bq1[1];
            float av[8] = {a0.x,a0.y,a0.z,a0.w,a1.x,a1.y,a1.z,a1.w};
#pragma unroll
            for (int i = 0; i < 8; i++) {
                uint64_t ap;
                asm("mov.b64 %0, {%1, %1};" : "=l"(ap) : "f"(av[i]));
                asm("fma.rn.f32x2 %0, %1, %2, %0;" : "+l"(acc2[i][0]) : "l"(ap), "l"(bp0));
                asm("fma.rn.f32x2 %0, %1, %2, %0;" : "+l"(acc2[i][1]) : "l"(ap), "l"(bp1));
                asm("fma.rn.f32x2 %0, %1, %2, %0;" : "+l"(acc2[i][2]) : "l"(ap), "l"(bp2));
                asm("fma.rn.f32x2 %0, %1, %2, %0;" : "+l"(acc2[i][3]) : "l"(ap), "l"(bp3));
            }
        }
    }
    // unpack to the scalar layout used by the proven epilogue
    float acc[8][8];
#pragma unroll
    for (int i = 0; i < 8; i++)
#pragma unroll
        for (int j = 0; j < 4; j++) {
            float lo, hi;
            asm("mov.b64 {%0, %1}, %2;" : "=f"(lo), "=f"(hi) : "l"(acc2[i][j]));
            acc[i][2*j]   = lo;
            acc[i][2*j+1] = hi;
        }

    float invn = 1.0f / (float)N;
#pragma unroll
    for (int i = 0; i < 8; i++) {
        int gi = row0 + ((i<4) ? (4*ty+i) : (64+4*ty+i-4));
#pragma unroll
        for (int j = 0; j < 8; j++) {
            int gj = col0 + ((j<4) ? (4*tx+j) : (64+4*tx+j-4));
            float val = acc[i][j]*invn + ((gi==gj)?1.0f:0.0f);
            g_A[(size_t)gi*N+gj] = val;
            if (bx > by) g_A[(size_t)gj*N+gi] = val;
        }
    }
}

// ---------------- SpMM 1: C = S * A ------------------------------------------
__global__ void k_spmm_AC() {
    int r = blockIdx.x, t = threadIdx.x;
    int s = g_rowptr[r], e = g_rowptr[r+1];
    float acc[8] = {0,0,0,0,0,0,0,0};
    for (int k = s; k < e; k++) {
        int c = g_colidx[k];
        float v = g_csrval[k];
        const float* xr = g_A + (size_t)c * N;
#pragma unroll
        for (int u = 0; u < 8; u++) acc[u] += v * xr[t + u*TPB];
    }
    float* yr = g_C + (size_t)r * N;
#pragma unroll
    for (int u = 0; u < 8; u++) yr[t + u*TPB] = acc[u];
}

// ---------------- transpose: CT = C^T ----------------------------------------
__global__ void k_tr_C_CT() {
    __shared__ float t[32][33];
    int bx = blockIdx.x*32, by = blockIdx.y*32;
    int x = bx + threadIdx.x;
#pragma unroll
    for (int j = 0; j < 32; j += 8)
        t[threadIdx.y+j][threadIdx.x] = g_C[(size_t)(by+threadIdx.y+j)*N + x];
    __syncthreads();
    int x2 = by + threadIdx.x;
#pragma unroll
    for (int j = 0; j < 32; j += 8)
        g_CT[(size_t)(bx+threadIdx.y+j)*N + x2] = t[threadIdx.x][threadIdx.y+j];
}

// ------- SpMM 2 fused: M = A + C + C^T + S*C^T ------------------------------
__global__ void k_spmm_M() {
    int r = blockIdx.x, t = threadIdx.x;
    int s = g_rowptr[r], e = g_rowptr[r+1];
    float acc[8] = {0,0,0,0,0,0,0,0};
    for (int k = s; k < e; k++) {
        int c = g_colidx[k];
        float v = g_csrval[k];
        const float* xr = g_CT + (size_t)c * N;
#pragma unroll
        for (int u = 0; u < 8; u++) acc[u] += v * xr[t + u*TPB];
    }
    const float* ar = g_A  + (size_t)r * N;
    const float* cr = g_C  + (size_t)r * N;
    const float* tr = g_CT + (size_t)r * N;
    float* mr = g_M + (size_t)r * N;
#pragma unroll
    for (int u = 0; u < 8; u++) {
        int i = t + u*TPB;
        mr[i] = ar[i] + cr[i] + tr[i] + acc[u];
    }
}

// ---------------- Lanczos: persistent, 1 barrier/iter, local beta ----------
__device__ __forceinline__ void gbar(unsigned int& ep) {
    ep++;
    __threadfence();
    __syncthreads();
    if (blockIdx.x == 0) {
        if (threadIdx.x > 0 && threadIdx.x < GRID) {
            while (g_arrive[threadIdx.x] < ep) __nanosleep(20);
        }
        __syncthreads();
        if (threadIdx.x == 0) g_release = ep;
    } else {
        if (threadIdx.x == 0) {
            g_arrive[blockIdx.x] = ep;
            while (g_release < ep) __nanosleep(20);
        }
    }
    __syncthreads();
    __threadfence();
}

__device__ __forceinline__ float sum_parts(const float* part, float* sred, float* sbc) {
    int tid = threadIdx.x, warp = tid >> 5, wl = tid & 31;
    float a = (tid < GRID) ? __ldcg(&part[tid]) : 0.f;
#pragma unroll
    for (int off = 16; off; off >>= 1) a += __shfl_down_sync(0xffffffffu, a, off);
    if (wl == 0) sred[warp] = a;
    __syncthreads();
    if (tid == 0) {
        float s = 0.f;
#pragma unroll
        for (int w = 0; w < 4; w++) s += sred[w];
        sbc[0] = s;
    }
    __syncthreads();
    return sbc[0];
}

__device__ __forceinline__ float block_sum(float p, float* sred, float* sbc) {
    int tid = threadIdx.x, warp = tid >> 5, wl = tid & 31;
#pragma unroll
    for (int off = 16; off; off >>= 1) p += __shfl_down_sync(0xffffffffu, p, off);
    if (wl == 0) sred[warp] = p;
    __syncthreads();
    if (tid == 0) {
        float s = 0.f;
#pragma unroll
        for (int w = 0; w < 8; w++) s += sred[w];
        sbc[0] = s;
    }
    __syncthreads();
    return sbc[0];
}

__global__ void __launch_bounds__(TPB) k_lanczos() {
    __shared__ __align__(16) float svbuf[2][N];
    __shared__ float shw[16];
    __shared__ float sred[8];
    __shared__ float sbc[1];

    const int tid = threadIdx.x, bid = blockIdx.x;
    const int q = tid >> 4, lane = tid & 15;
    const int row = bid*16 + q;
    const int myrow = bid*16 + tid;
    unsigned int ep = 0;

    if (tid < 16) {
        unsigned int h = (unsigned int)myrow * 2654435761u + 0x9E3779B9u;
        h ^= h>>16; h *= 0x85ebca6bu; h ^= h>>13; h *= 0xc2b2ae35u; h ^= h>>16;
        g_u[1][myrow] = (float)(h & 0xffffu) * (1.0f/65536.0f) + 0.0625f;
    }
    gbar(ep);

    float* svc = svbuf[0];
    float* svp = svbuf[1];
    {
        float p = 0.f;
        for (int i = tid; i < N; i += TPB) {
            float x = __ldcg(&g_u[1][i]);
            svc[i] = x;
            svp[i] = 0.f;
            p += x * x;
        }
        float n0 = block_sum(p, sred, sbc);
        float inv0 = rsqrtf(n0);
        for (int i = tid; i < N; i += TPB) svc[i] *= inv0;
        __syncthreads();
    }
    float beta_p = 0.f;

    for (int j = 0; j < KL; j++) {
        const int b = j & 1;
        const float4* M4  = ((const float4*)g_M) + (size_t)row * (N/4);
        const float4* sv4 = (const float4*)svc;
        float s = 0.f;
#pragma unroll
        for (int t = 0; t < 16; t++) {
            int qi = lane*2 + t*32;
            float4 m0 = M4[qi], m1 = M4[qi+1];
            float4 x0 = sv4[qi], x1 = sv4[qi+1];
            s += m0.x*x0.x + m0.y*x0.y + m0.z*x0.z + m0.w*x0.w
               + m1.x*x1.x + m1.y*x1.y + m1.z*x1.z + m1.w*x1.w;
        }
#pragma unroll
        for (int off = 8; off; off >>= 1) s += __shfl_down_sync(0xffffffffu, s, off, 16);
        if (lane == 0) shw[q] = s;
        __syncthreads();

        float pa = 0.f;
        if (tid < 16) {
            float uval = shw[tid];
            g_u[b][myrow] = uval;
            pa = uval * svc[myrow];
        }
#pragma unroll
        for (int off = 8; off; off >>= 1) pa += __shfl_down_sync(0xffffffffu, pa, off, 16);
        if (tid == 0) g_part[b][bid] = pa;
        gbar(ep);

        float alpha = sum_parts(g_part[b], sred, sbc);
        float pw = 0.f;
        for (int i = tid; i < N; i += TPB) {
            float w = __ldcg(&g_u[b][i]) - alpha*svc[i] - beta_p*svp[i];
            svp[i] = w;
            pw += w * w;
        }
        float nw = block_sum(pw, sred, sbc);
        float beta = sqrtf(fmaxf(nw, 1e-30f));
        if (bid == 0 && tid == 0) { g_alpha[j] = alpha; g_betav[j] = beta; }
        float invb = 1.0f / beta;
        for (int i = tid; i < N; i += TPB) svp[i] *= invb;
        __syncthreads();
        float* t = svc; svc = svp; svp = t;
        beta_p = beta;
    }
}

// ------- extremes: double Sturm count, 32-way multisection, 2 warps --------
__global__ void k_extremes(float* out) {
    __shared__ double sa[KL], sb[KL];
    __shared__ double sbounds[2];
    __shared__ double res[2];
    int tid = threadIdx.x;
    int warp = tid >> 5, lane = tid & 31;

    for (int i = tid; i < KL; i += 64) {
        sa[i] = (double)g_alpha[i];
        sb[i] = (double)g_betav[i];
    }
    __syncthreads();
    if (tid == 0) {
        double lo = 1e300, hi = -1e300;
        for (int i = 0; i < KL; i++) {
            double bl = (i > 0)    ? fabs(sb[i-1]) : 0.0;
            double br = (i < KL-1) ? fabs(sb[i])   : 0.0;
            double a = sa[i];
            if (a - bl - br < lo) lo = a - bl - br;
            if (a + bl + br > hi) hi = a + bl + br;
        }
        sbounds[0] = lo; sbounds[1] = hi;
    }
    __syncthreads();

    int target = (warp == 0) ? KL : 1;
    double lo = sbounds[0], hi = sbounds[1];

    for (int step = 0; step < 7; step++) {
        double w = (hi - lo) * (1.0 / 33.0);
        double x = lo + w * (double)(lane + 1);
        double d = sa[0] - x;
        int cnt = (d < 0.0);
        for (int i = 1; i < KL; i++) {
            double den = d;
            if (fabs(den) < 1e-280) den = (den < 0.0) ? -1e-280 : 1e-280;
            d = (sa[i] - x) - sb[i-1]*sb[i-1] / den;
            cnt += (d < 0.0);
        }
        unsigned mask = __ballot_sync(0xffffffffu, cnt >= target);
        int first = (mask == 0u) ? 32 : (__ffs(mask) - 1);
        if (first < 32) hi = lo + w * (double)(first + 1);
        lo = lo + w * (double)first;
    }
    if (lane == 0) res[warp] = 0.5 * (lo + hi);
    __syncthreads();
    if (tid == 0) {
        double lmax = fmax(res[0], 1e-12);
        double lmin = fmax(res[1], 1e-12);
        out[0] = (float)(log(lmax) - log(lmin));
    }
}

// ---------------- launch ------------------------------------------------------
extern "C" void kernel_launch(void* const* d_in, const int* in_sizes, int n_in,
                              void* d_out, int out_size) {
    const float* pred = (const float*)d_in[0];
    const float* scl  = (const float*)d_in[1];
    const float* Af   = (const float*)d_in[2];
    const int* frows  = (const int*)d_in[3];
    const int* fcols  = (const int*)d_in[4];
    float* out = (float*)d_out;

    k_prep <<<NNZ/TPB, TPB>>>(pred, scl);
    k_count<<<NNZ/TPB, TPB>>>(frows);
    k_scan <<<1, 256>>>();
    k_fill <<<NNZ/TPB, TPB>>>(frows, fcols);

    k_syrk<<<dim3(16,16), 256>>>(Af);

    k_spmm_AC <<<N, TPB>>>();
    k_tr_C_CT <<<dim3(64,64), dim3(32,8)>>>();
    k_spmm_M  <<<N, TPB>>>();

    k_lanczos <<<GRID, TPB>>>();
    k_extremes<<<1, 64>>>(out);
}

// round 12
// speedup vs baseline: 11.3321x; 1.0803x over previous
#include <cuda_runtime.h>
#include <cstdint>
#include <math.h>

#define N     2048
#define NNZ   32768
#define KL    64
#define GRID  128
#define TPB   256
#define BK    8

// ---------------- scratch (device globals; no allocation) ------------------
__device__ float g_A[N*N];
__device__ float g_C[N*N];
__device__ float g_CT[N*N];
__device__ float g_M[N*N];

__device__ float g_vals[NNZ];
__device__ int   g_rowptr[N+1];
__device__ int   g_cnt[N];
__device__ int   g_colidx[NNZ];
__device__ float g_csrval[NNZ];

__device__ float g_u[2][N];
__device__ float g_part[2][GRID];
__device__ float g_alpha[KL];
__device__ float g_betav[KL];
__device__ volatile unsigned int g_arrive[GRID];
__device__ volatile unsigned int g_release;

// ---------------- CSR build ------------------------------------------------
__global__ void k_prep(const float* __restrict__ pred, const float* __restrict__ scl) {
    int i = blockIdx.x * blockDim.x + threadIdx.x;
    if (i < NNZ) g_vals[i] = pred[i] * scl[i];
    if (i < N)   g_cnt[i] = 0;
    if (blockIdx.x == 0) {
        if (threadIdx.x < GRID) g_arrive[threadIdx.x] = 0;
        if (threadIdx.x == 0)   g_release = 0;
    }
}
__global__ void k_count(const int* __restrict__ rows) {
    int i = blockIdx.x * blockDim.x + threadIdx.x;
    if (i < NNZ) atomicAdd(&g_cnt[rows[i]], 1);
}
__global__ void k_scan() {
    int tid = threadIdx.x;
    int lane = tid & 31, warp = tid >> 5;
    int v[8]; int loc = 0;
#pragma unroll
    for (int u = 0; u < 8; u++) { v[u] = g_cnt[tid*8 + u]; loc += v[u]; }
    int sc = loc;
#pragma unroll
    for (int off = 1; off < 32; off <<= 1) {
        int nb = __shfl_up_sync(0xffffffffu, sc, off);
        if (lane >= off) sc += nb;
    }
    __shared__ int wsum[8];
    if (lane == 31) wsum[warp] = sc;
    __syncthreads();
    if (tid == 0) {
        int a = 0;
#pragma unroll
        for (int w = 0; w < 8; w++) { int t = wsum[w]; wsum[w] = a; a += t; }
    }
    __syncthreads();
    int run = sc - loc + wsum[warp];
#pragma unroll
    for (int u = 0; u < 8; u++) {
        g_rowptr[tid*8 + u] = run;
        g_cnt[tid*8 + u]    = run;
        run += v[u];
    }
    if (tid == 255) g_rowptr[N] = run;
}
__global__ void k_fill(const int* __restrict__ rows, const int* __restrict__ cols) {
    int i = blockIdx.x * blockDim.x + threadIdx.x;
    if (i < NNZ) {
        int p = atomicAdd(&g_cnt[rows[i]], 1);
        g_colidx[p] = cols[i];
        g_csrval[p] = g_vals[i];
    }
}

// ------ SYRK: A = Af*Af^T / N + I  (packed f32x2 FFMA2 inner loop) ---------
__global__ void __launch_bounds__(256) k_syrk(const float* __restrict__ Af) {
    int bx = blockIdx.x, by = blockIdx.y;
    if (bx < by) return;
    __shared__ __align__(16) float As[BK][132];
    __shared__ __align__(16) float Bs[BK][132];
    int tid = threadIdx.x;
    int tx = tid & 15, ty = tid >> 4;
    int row0 = by * 128, col0 = bx * 128;

    uint64_t acc2[8][4];
#pragma unroll
    for (int i = 0; i < 8; i++)
#pragma unroll
        for (int j = 0; j < 4; j++) acc2[i][j] = 0ull;

    int lr = tid >> 1;
    int lk = (tid & 1) * 4;
    const float* abase = Af + (size_t)(row0 + lr) * N + lk;
    const float* bbase = Af + (size_t)(col0 + lr) * N + lk;
    float4 pa = *(const float4*)abase;
    float4 pb = *(const float4*)bbase;

    for (int kk = 0; kk < N; kk += BK) {
        __syncthreads();
        As[lk+0][lr]=pa.x; As[lk+1][lr]=pa.y; As[lk+2][lr]=pa.z; As[lk+3][lr]=pa.w;
        Bs[lk+0][lr]=pb.x; Bs[lk+1][lr]=pb.y; Bs[lk+2][lr]=pb.z; Bs[lk+3][lr]=pb.w;
        __syncthreads();
        if (kk + BK < N) {
            pa = *(const float4*)(abase + kk + BK);
            pb = *(const float4*)(bbase + kk + BK);
        }
#pragma unroll
        for (int k = 0; k < BK; k++) {
            float4 a0 = *(const float4*)&As[k][4*ty];
            float4 a1 = *(const float4*)&As[k][64+4*ty];
            const uint64_t* bq0 = (const uint64_t*)&Bs[k][4*tx];
            const uint64_t* bq1 = (const uint64_t*)&Bs[k][64+4*tx];
            uint64_t bp0 = bq0[0], bp1 = bq0[1], bp2 = bq1[0], bp3 = bq1[1];
            float av[8] = {a0.x,a0.y,a0.z,a0.w,a1.x,a1.y,a1.z,a1.w};
#pragma unroll
            for (int i = 0; i < 8; i++) {
                uint64_t ap;
                asm("mov.b64 %0, {%1, %1};" : "=l"(ap) : "f"(av[i]));
                asm("fma.rn.f32x2 %0, %1, %2, %0;" : "+l"(acc2[i][0]) : "l"(ap), "l"(bp0));
                asm("fma.rn.f32x2 %0, %1, %2, %0;" : "+l"(acc2[i][1]) : "l"(ap), "l"(bp1));
                asm("fma.rn.f32x2 %0, %1, %2, %0;" : "+l"(acc2[i][2]) : "l"(ap), "l"(bp2));
                asm("fma.rn.f32x2 %0, %1, %2, %0;" : "+l"(acc2[i][3]) : "l"(ap), "l"(bp3));
            }
        }
    }
    float acc[8][8];
#pragma unroll
    for (int i = 0; i < 8; i++)
#pragma unroll
        for (int j = 0; j < 4; j++) {
            float lo, hi;
            asm("mov.b64 {%0, %1}, %2;" : "=f"(lo), "=f"(hi) : "l"(acc2[i][j]));
            acc[i][2*j]   = lo;
            acc[i][2*j+1] = hi;
        }

    float invn = 1.0f / (float)N;
#pragma unroll
    for (int i = 0; i < 8; i++) {
        int gi = row0 + ((i<4) ? (4*ty+i) : (64+4*ty+i-4));
#pragma unroll
        for (int j = 0; j < 8; j++) {
            int gj = col0 + ((j<4) ? (4*tx+j) : (64+4*tx+j-4));
            float val = acc[i][j]*invn + ((gi==gj)?1.0f:0.0f);
            g_A[(size_t)gi*N+gj] = val;
            if (bx > by) g_A[(size_t)gj*N+gi] = val;
        }
    }
}

// ---------------- SpMM 1: C = S * A ------------------------------------------
__global__ void k_spmm_AC() {
    int r = blockIdx.x, t = threadIdx.x;
    int s = g_rowptr[r], e = g_rowptr[r+1];
    float acc[8] = {0,0,0,0,0,0,0,0};
    for (int k = s; k < e; k++) {
        int c = g_colidx[k];
        float v = g_csrval[k];
        const float* xr = g_A + (size_t)c * N;
#pragma unroll
        for (int u = 0; u < 8; u++) acc[u] += v * xr[t + u*TPB];
    }
    float* yr = g_C + (size_t)r * N;
#pragma unroll
    for (int u = 0; u < 8; u++) yr[t + u*TPB] = acc[u];
}

// ---------------- transpose: CT = C^T ----------------------------------------
__global__ void k_tr_C_CT() {
    __shared__ float t[32][33];
    int bx = blockIdx.x*32, by = blockIdx.y*32;
    int x = bx + threadIdx.x;
#pragma unroll
    for (int j = 0; j < 32; j += 8)
        t[threadIdx.y+j][threadIdx.x] = g_C[(size_t)(by+threadIdx.y+j)*N + x];
    __syncthreads();
    int x2 = by + threadIdx.x;
#pragma unroll
    for (int j = 0; j < 32; j += 8)
        g_CT[(size_t)(bx+threadIdx.y+j)*N + x2] = t[threadIdx.x][threadIdx.y+j];
}

// ------- SpMM 2 fused: M = A + C + C^T + S*C^T ------------------------------
__global__ void k_spmm_M() {
    int r = blockIdx.x, t = threadIdx.x;
    int s = g_rowptr[r], e = g_rowptr[r+1];
    float acc[8] = {0,0,0,0,0,0,0,0};
    for (int k = s; k < e; k++) {
        int c = g_colidx[k];
        float v = g_csrval[k];
        const float* xr = g_CT + (size_t)c * N;
#pragma unroll
        for (int u = 0; u < 8; u++) acc[u] += v * xr[t + u*TPB];
    }
    const float* ar = g_A  + (size_t)r * N;
    const float* cr = g_C  + (size_t)r * N;
    const float* tr = g_CT + (size_t)r * N;
    float* mr = g_M + (size_t)r * N;
#pragma unroll
    for (int u = 0; u < 8; u++) {
        int i = t + u*TPB;
        mr[i] = ar[i] + cr[i] + tr[i] + acc[u];
    }
}

// ---------------- Lanczos: persistent, 1 barrier/iter, local beta ----------
__device__ __forceinline__ void gbar(unsigned int& ep) {
    ep++;
    __threadfence();
    __syncthreads();
    if (blockIdx.x == 0) {
        if (threadIdx.x > 0 && threadIdx.x < GRID) {
            while (g_arrive[threadIdx.x] < ep) { }
        }
        __syncthreads();
        if (threadIdx.x == 0) g_release = ep;
    } else {
        if (threadIdx.x == 0) {
            g_arrive[blockIdx.x] = ep;
            while (g_release < ep) { }
        }
    }
    __syncthreads();
    __threadfence();
}

__device__ __forceinline__ float sum_parts(const float* part, float* sred, float* sbc) {
    int tid = threadIdx.x, warp = tid >> 5, wl = tid & 31;
    float a = (tid < GRID) ? __ldcg(&part[tid]) : 0.f;
#pragma unroll
    for (int off = 16; off; off >>= 1) a += __shfl_down_sync(0xffffffffu, a, off);
    if (wl == 0) sred[warp] = a;
    __syncthreads();
    if (tid == 0) {
        float s = 0.f;
#pragma unroll
        for (int w = 0; w < 4; w++) s += sred[w];
        sbc[0] = s;
    }
    __syncthreads();
    return sbc[0];
}

__device__ __forceinline__ float block_sum(float p, float* sred, float* sbc) {
    int tid = threadIdx.x, warp = tid >> 5, wl = tid & 31;
#pragma unroll
    for (int off = 16; off; off >>= 1) p += __shfl_down_sync(0xffffffffu, p, off);
    if (wl == 0) sred[warp] = p;
    __syncthreads();
    if (tid == 0) {
        float s = 0.f;
#pragma unroll
        for (int w = 0; w < 8; w++) s += sred[w];
        sbc[0] = s;
    }
    __syncthreads();
    return sbc[0];
}

__global__ void __launch_bounds__(TPB) k_lanczos() {
    __shared__ __align__(16) float svbuf[2][N];
    __shared__ float shw[16];
    __shared__ float sred[8];
    __shared__ float sbc[1];

    const int tid = threadIdx.x, bid = blockIdx.x;
    const int q = tid >> 4, lane = tid & 15;
    const int row = bid*16 + q;
    const int myrow = bid*16 + tid;
    unsigned int ep = 0;

    if (tid < 16) {
        unsigned int h = (unsigned int)myrow * 2654435761u + 0x9E3779B9u;
        h ^= h>>16; h *= 0x85ebca6bu; h ^= h>>13; h *= 0xc2b2ae35u; h ^= h>>16;
        g_u[1][myrow] = (float)(h & 0xffffu) * (1.0f/65536.0f) + 0.0625f;
    }
    gbar(ep);

    float* svc = svbuf[0];
    float* svp = svbuf[1];
    {
        float p = 0.f;
        for (int i = tid; i < N; i += TPB) {
            float x = __ldcg(&g_u[1][i]);
            svc[i] = x;
            svp[i] = 0.f;
            p += x * x;
        }
        float n0 = block_sum(p, sred, sbc);
        float inv0 = rsqrtf(n0);
        for (int i = tid; i < N; i += TPB) svc[i] *= inv0;
        __syncthreads();
    }
    float beta_p = 0.f;

    for (int j = 0; j < KL; j++) {
        const int b = j & 1;
        const float4* M4  = ((const float4*)g_M) + (size_t)row * (N/4);
        const float4* sv4 = (const float4*)svc;
        float s = 0.f;
#pragma unroll
        for (int t = 0; t < 16; t++) {
            int qi = lane*2 + t*32;
            float4 m0 = M4[qi], m1 = M4[qi+1];
            float4 x0 = sv4[qi], x1 = sv4[qi+1];
            s += m0.x*x0.x + m0.y*x0.y + m0.z*x0.z + m0.w*x0.w
               + m1.x*x1.x + m1.y*x1.y + m1.z*x1.z + m1.w*x1.w;
        }
#pragma unroll
        for (int off = 8; off; off >>= 1) s += __shfl_down_sync(0xffffffffu, s, off, 16);
        if (lane == 0) shw[q] = s;
        __syncthreads();

        float pa = 0.f;
        if (tid < 16) {
            float uval = shw[tid];
            g_u[b][myrow] = uval;
            pa = uval * svc[myrow];
        }
#pragma unroll
        for (int off = 8; off; off >>= 1) pa += __shfl_down_sync(0xffffffffu, pa, off, 16);
        if (tid == 0) g_part[b][bid] = pa;
        gbar(ep);

        float alpha = sum_parts(g_part[b], sred, sbc);
        float pw = 0.f;
        for (int i = tid; i < N; i += TPB) {
            float w = __ldcg(&g_u[b][i]) - alpha*svc[i] - beta_p*svp[i];
            svp[i] = w;
            pw += w * w;
        }
        float nw = block_sum(pw, sred, sbc);
        float beta = sqrtf(fmaxf(nw, 1e-30f));
        if (bid == 0 && tid == 0) { g_alpha[j] = alpha; g_betav[j] = beta; }
        float invb = 1.0f / beta;
        for (int i = tid; i < N; i += TPB) svp[i] *= invb;
        __syncthreads();
        float* t = svc; svc = svp; svp = t;
        beta_p = beta;
    }
}

// ------- extremes: double Sturm count, 32-way multisection, 4 steps --------
__global__ void k_extremes(float* out) {
    __shared__ double sa[KL], sb[KL];
    __shared__ double sbounds[2];
    __shared__ double res[2];
    int tid = threadIdx.x;
    int warp = tid >> 5, lane = tid & 31;

    for (int i = tid; i < KL; i += 64) {
        sa[i] = (double)g_alpha[i];
        sb[i] = (double)g_betav[i];
    }
    __syncthreads();
    if (tid == 0) {
        double lo = 1e300, hi = -1e300;
        for (int i = 0; i < KL; i++) {
            double bl = (i > 0)    ? fabs(sb[i-1]) : 0.0;
            double br = (i < KL-1) ? fabs(sb[i])   : 0.0;
            double a = sa[i];
            if (a - bl - br < lo) lo = a - bl - br;
            if (a + bl + br > hi) hi = a + bl + br;
        }
        sbounds[0] = lo; sbounds[1] = hi;
    }
    __syncthreads();

    int target = (warp == 0) ? KL : 1;
    double lo = sbounds[0], hi = sbounds[1];

    for (int step = 0; step < 4; step++) {
        double w = (hi - lo) * (1.0 / 33.0);
        double x = lo + w * (double)(lane + 1);
        double d = sa[0] - x;
        int cnt = (d < 0.0);
        for (int i = 1; i < KL; i++) {
            double den = d;
            if (fabs(den) < 1e-280) den = (den < 0.0) ? -1e-280 : 1e-280;
            d = (sa[i] - x) - sb[i-1]*sb[i-1] / den;
            cnt += (d < 0.0);
        }
        unsigned mask = __ballot_sync(0xffffffffu, cnt >= target);
        int first = (mask == 0u) ? 32 : (__ffs(mask) - 1);
        if (first < 32) hi = lo + w * (double)(first + 1);
        lo = lo + w * (double)first;
    }
    if (lane == 0) res[warp] = 0.5 * (lo + hi);
    __syncthreads();
    if (tid == 0) {
        double lmax = fmax(res[0], 1e-12);
        double lmin = fmax(res[1], 1e-12);
        out[0] = (float)(log(lmax) - log(lmin));
    }
}

// ---------------- launch ------------------------------------------------------
extern "C" void kernel_launch(void* const* d_in, const int* in_sizes, int n_in,
                              void* d_out, int out_size) {
    const float* pred = (const float*)d_in[0];
    const float* scl  = (const float*)d_in[1];
    const float* Af   = (const float*)d_in[2];
    const int* frows  = (const int*)d_in[3];
    const int* fcols  = (const int*)d_in[4];
    float* out = (float*)d_out;

    k_prep <<<NNZ/TPB, TPB>>>(pred, scl);
    k_count<<<NNZ/TPB, TPB>>>(frows);
    k_scan <<<1, 256>>>();
    k_syrk <<<dim3(16,16), 256>>>(Af);   // 4th launch -> captured by ncu
    k_fill <<<NNZ/TPB, TPB>>>(frows, fcols);

    k_spmm_AC <<<N, TPB>>>();
    k_tr_C_CT <<<dim3(64,64), dim3(32,8)>>>();
    k_spmm_M  <<<N, TPB>>>();

    k_lanczos <<<GRID, TPB>>>();
    k_extremes<<<1, 64>>>(out);
}

// round 13
// speedup vs baseline: 14.0248x; 1.2376x over previous
#include <cuda_runtime.h>
#include <cstdint>
#include <math.h>

#define N     2048
#define NNZ   32768
#define KL    64
#define GRID  128
#define TPB   256
#define BKS   16           // k-tile for SYRK
#define SYRK_TILES 136

// ---------------- scratch (device globals; no allocation) ------------------
__device__ float g_A[N*N];
__device__ float g_C[N*N];
__device__ float g_CT[N*N];
__device__ float g_M[N*N];

__device__ float g_vals[NNZ];
__device__ int   g_rowptr[N+1];
__device__ int   g_cnt[N];
__device__ int   g_colidx[NNZ];
__device__ float g_csrval[NNZ];

__device__ float g_u[2][N];
__device__ float g_part[2][GRID];
__device__ float g_alpha[KL];
__device__ float g_betav[KL];
__device__ volatile unsigned int g_arrive[GRID];
__device__ volatile unsigned int g_release;

// ---------------- CSR build ------------------------------------------------
__global__ void k_prep(const float* __restrict__ pred, const float* __restrict__ scl) {
    int i = blockIdx.x * blockDim.x + threadIdx.x;
    if (i < NNZ) g_vals[i] = pred[i] * scl[i];
    if (i < N)   g_cnt[i] = 0;
    if (blockIdx.x == 0) {
        if (threadIdx.x < GRID) g_arrive[threadIdx.x] = 0;
        if (threadIdx.x == 0)   g_release = 0;
    }
}
__global__ void k_count(const int* __restrict__ rows) {
    int i = blockIdx.x * blockDim.x + threadIdx.x;
    if (i < NNZ) atomicAdd(&g_cnt[rows[i]], 1);
}
__global__ void k_scan() {
    int tid = threadIdx.x;
    int lane = tid & 31, warp = tid >> 5;
    int v[8]; int loc = 0;
#pragma unroll
    for (int u = 0; u < 8; u++) { v[u] = g_cnt[tid*8 + u]; loc += v[u]; }
    int sc = loc;
#pragma unroll
    for (int off = 1; off < 32; off <<= 1) {
        int nb = __shfl_up_sync(0xffffffffu, sc, off);
        if (lane >= off) sc += nb;
    }
    __shared__ int wsum[8];
    if (lane == 31) wsum[warp] = sc;
    __syncthreads();
    if (tid == 0) {
        int a = 0;
#pragma unroll
        for (int w = 0; w < 8; w++) { int t = wsum[w]; wsum[w] = a; a += t; }
    }
    __syncthreads();
    int run = sc - loc + wsum[warp];
#pragma unroll
    for (int u = 0; u < 8; u++) {
        g_rowptr[tid*8 + u] = run;
        g_cnt[tid*8 + u]    = run;
        run += v[u];
    }
    if (tid == 255) g_rowptr[N] = run;
}
__global__ void k_fill(const int* __restrict__ rows, const int* __restrict__ cols) {
    int i = blockIdx.x * blockDim.x + threadIdx.x;
    if (i < NNZ) {
        int p = atomicAdd(&g_cnt[rows[i]], 1);
        g_colidx[p] = cols[i];
        g_csrval[p] = g_vals[i];
    }
}

// ------ SYRK: A = Af*Af^T / N + I ------------------------------------------
// 136 CTAs (one wave), double-buffered smem, BK=16, one sync per k-tile.
__global__ void __launch_bounds__(256) k_syrk(const float* __restrict__ Af) {
    int rem = blockIdx.x, by = 0;
    while (rem >= 16 - by) { rem -= 16 - by; by++; }
    const int bx = by + rem;

    __shared__ __align__(16) float As[2][BKS][132];
    __shared__ __align__(16) float Bs[2][BKS][132];
    const int tid = threadIdx.x;
    const int tx = tid & 15, ty = tid >> 4;
    const int row0 = by * 128, col0 = bx * 128;

    uint64_t acc2[8][4];
#pragma unroll
    for (int i = 0; i < 8; i++)
#pragma unroll
        for (int j = 0; j < 4; j++) acc2[i][j] = 0ull;

    const int lr = tid >> 1;
    const int lk = (tid & 1) * 8;
    const float* abase = Af + (size_t)(row0 + lr) * N + lk;
    const float* bbase = Af + (size_t)(col0 + lr) * N + lk;

    float4 pa0 = *(const float4*)(abase);
    float4 pa1 = *(const float4*)(abase + 4);
    float4 pb0 = *(const float4*)(bbase);
    float4 pb1 = *(const float4*)(bbase + 4);
    {   // stage tile 0 into buffer 0
        As[0][lk+0][lr]=pa0.x; As[0][lk+1][lr]=pa0.y; As[0][lk+2][lr]=pa0.z; As[0][lk+3][lr]=pa0.w;
        As[0][lk+4][lr]=pa1.x; As[0][lk+5][lr]=pa1.y; As[0][lk+6][lr]=pa1.z; As[0][lk+7][lr]=pa1.w;
        Bs[0][lk+0][lr]=pb0.x; Bs[0][lk+1][lr]=pb0.y; Bs[0][lk+2][lr]=pb0.z; Bs[0][lk+3][lr]=pb0.w;
        Bs[0][lk+4][lr]=pb1.x; Bs[0][lk+5][lr]=pb1.y; Bs[0][lk+6][lr]=pb1.z; Bs[0][lk+7][lr]=pb1.w;
    }
    __syncthreads();

    const int NIT = N / BKS;       // 128
    for (int it = 0; it < NIT; it++) {
        const int buf = it & 1;
        if (it + 1 < NIT) {        // prefetch next tile to registers
            int off = (it + 1) * BKS;
            pa0 = *(const float4*)(abase + off);
            pa1 = *(const float4*)(abase + off + 4);
            pb0 = *(const float4*)(bbase + off);
            pb1 = *(const float4*)(bbase + off + 4);
        }
#pragma unroll
        for (int k = 0; k < BKS; k++) {
            float4 a0 = *(const float4*)&As[buf][k][4*tx*0 + 4*ty];
            float4 a1 = *(const float4*)&As[buf][k][64+4*ty];
            const uint64_t* bq0 = (const uint64_t*)&Bs[buf][k][4*tx];
            const uint64_t* bq1 = (const uint64_t*)&Bs[buf][k][64+4*tx];
            uint64_t bp0 = bq0[0], bp1 = bq0[1], bp2 = bq1[0], bp3 = bq1[1];
            float av[8] = {a0.x,a0.y,a0.z,a0.w,a1.x,a1.y,a1.z,a1.w};
#pragma unroll
            for (int i = 0; i < 8; i++) {
                uint64_t ap;
                asm("mov.b64 %0, {%1, %1};" : "=l"(ap) : "f"(av[i]));
                asm("fma.rn.f32x2 %0, %1, %2, %0;" : "+l"(acc2[i][0]) : "l"(ap), "l"(bp0));
                asm("fma.rn.f32x2 %0, %1, %2, %0;" : "+l"(acc2[i][1]) : "l"(ap), "l"(bp1));
                asm("fma.rn.f32x2 %0, %1, %2, %0;" : "+l"(acc2[i][2]) : "l"(ap), "l"(bp2));
                asm("fma.rn.f32x2 %0, %1, %2, %0;" : "+l"(acc2[i][3]) : "l"(ap), "l"(bp3));
            }
        }
        if (it + 1 < NIT) {        // stage prefetched tile into the idle buffer
            const int nb = buf ^ 1;
            As[nb][lk+0][lr]=pa0.x; As[nb][lk+1][lr]=pa0.y; As[nb][lk+2][lr]=pa0.z; As[nb][lk+3][lr]=pa0.w;
            As[nb][lk+4][lr]=pa1.x; As[nb][lk+5][lr]=pa1.y; As[nb][lk+6][lr]=pa1.z; As[nb][lk+7][lr]=pa1.w;
            Bs[nb][lk+0][lr]=pb0.x; Bs[nb][lk+1][lr]=pb0.y; Bs[nb][lk+2][lr]=pb0.z; Bs[nb][lk+3][lr]=pb0.w;
            Bs[nb][lk+4][lr]=pb1.x; Bs[nb][lk+5][lr]=pb1.y; Bs[nb][lk+6][lr]=pb1.z; Bs[nb][lk+7][lr]=pb1.w;
        }
        __syncthreads();
    }

    float acc[8][8];
#pragma unroll
    for (int i = 0; i < 8; i++)
#pragma unroll
        for (int j = 0; j < 4; j++) {
            float lo, hi;
            asm("mov.b64 {%0, %1}, %2;" : "=f"(lo), "=f"(hi) : "l"(acc2[i][j]));
            acc[i][2*j]   = lo;
            acc[i][2*j+1] = hi;
        }

    float invn = 1.0f / (float)N;
#pragma unroll
    for (int i = 0; i < 8; i++) {
        int gi = row0 + ((i<4) ? (4*ty+i) : (64+4*ty+i-4));
#pragma unroll
        for (int j = 0; j < 8; j++) {
            int gj = col0 + ((j<4) ? (4*tx+j) : (64+4*tx+j-4));
            float val = acc[i][j]*invn + ((gi==gj)?1.0f:0.0f);
            g_A[(size_t)gi*N+gj] = val;
            if (bx > by) g_A[(size_t)gj*N+gi] = val;
        }
    }
}

// ---------------- SpMM 1: C = S * A ------------------------------------------
__global__ void k_spmm_AC() {
    int r = blockIdx.x, t = threadIdx.x;
    int s = g_rowptr[r], e = g_rowptr[r+1];
    float acc[8] = {0,0,0,0,0,0,0,0};
    for (int k = s; k < e; k++) {
        int c = g_colidx[k];
        float v = g_csrval[k];
        const float* xr = g_A + (size_t)c * N;
#pragma unroll
        for (int u = 0; u < 8; u++) acc[u] += v * xr[t + u*TPB];
    }
    float* yr = g_C + (size_t)r * N;
#pragma unroll
    for (int u = 0; u < 8; u++) yr[t + u*TPB] = acc[u];
}

// ---------------- transpose: CT = C^T ----------------------------------------
__global__ void k_tr_C_CT() {
    __shared__ float t[32][33];
    int bx = blockIdx.x*32, by = blockIdx.y*32;
    int x = bx + threadIdx.x;
#pragma unroll
    for (int j = 0; j < 32; j += 8)
        t[threadIdx.y+j][threadIdx.x] = g_C[(size_t)(by+threadIdx.y+j)*N + x];
    __syncthreads();
    int x2 = by + threadIdx.x;
#pragma unroll
    for (int j = 0; j < 32; j += 8)
        g_CT[(size_t)(bx+threadIdx.y+j)*N + x2] = t[threadIdx.x][threadIdx.y+j];
}

// ------- SpMM 2 fused: M = A + C + C^T + S*C^T ------------------------------
__global__ void k_spmm_M() {
    int r = blockIdx.x, t = threadIdx.x;
    int s = g_rowptr[r], e = g_rowptr[r+1];
    float acc[8] = {0,0,0,0,0,0,0,0};
    for (int k = s; k < e; k++) {
        int c = g_colidx[k];
        float v = g_csrval[k];
        const float* xr = g_CT + (size_t)c * N;
#pragma unroll
        for (int u = 0; u < 8; u++) acc[u] += v * xr[t + u*TPB];
    }
    const float* ar = g_A  + (size_t)r * N;
    const float* cr = g_C  + (size_t)r * N;
    const float* tr = g_CT + (size_t)r * N;
    float* mr = g_M + (size_t)r * N;
#pragma unroll
    for (int u = 0; u < 8; u++) {
        int i = t + u*TPB;
        mr[i] = ar[i] + cr[i] + tr[i] + acc[u];
    }
}

// ---------------- Lanczos: persistent, 1 barrier/iter, local beta ----------
__device__ __forceinline__ void gbar(unsigned int& ep) {
    ep++;
    __threadfence();
    __syncthreads();
    if (blockIdx.x == 0) {
        if (threadIdx.x > 0 && threadIdx.x < GRID) {
            while (g_arrive[threadIdx.x] < ep) { }
        }
        __syncthreads();
        if (threadIdx.x == 0) g_release = ep;
    } else {
        if (threadIdx.x == 0) {
            g_arrive[blockIdx.x] = ep;
            while (g_release < ep) { }
        }
    }
    __syncthreads();
    __threadfence();
}

__device__ __forceinline__ float sum_parts(const float* part, float* sred, float* sbc) {
    int tid = threadIdx.x, warp = tid >> 5, wl = tid & 31;
    float a = (tid < GRID) ? __ldcg(&part[tid]) : 0.f;
#pragma unroll
    for (int off = 16; off; off >>= 1) a += __shfl_down_sync(0xffffffffu, a, off);
    if (wl == 0) sred[warp] = a;
    __syncthreads();
    if (tid == 0) {
        float s = 0.f;
#pragma unroll
        for (int w = 0; w < 4; w++) s += sred[w];
        sbc[0] = s;
    }
    __syncthreads();
    return sbc[0];
}

__device__ __forceinline__ float block_sum(float p, float* sred, float* sbc) {
    int tid = threadIdx.x, warp = tid >> 5, wl = tid & 31;
#pragma unroll
    for (int off = 16; off; off >>= 1) p += __shfl_down_sync(0xffffffffu, p, off);
    if (wl == 0) sred[warp] = p;
    __syncthreads();
    if (tid == 0) {
        float s = 0.f;
#pragma unroll
        for (int w = 0; w < 8; w++) s += sred[w];
        sbc[0] = s;
    }
    __syncthreads();
    return sbc[0];
}

__global__ void __launch_bounds__(TPB) k_lanczos() {
    __shared__ __align__(16) float svbuf[2][N];
    __shared__ float shw[16];
    __shared__ float sred[8];
    __shared__ float sbc[1];

    const int tid = threadIdx.x, bid = blockIdx.x;
    const int q = tid >> 4, lane = tid & 15;
    const int row = bid*16 + q;
    const int myrow = bid*16 + tid;
    unsigned int ep = 0;

    if (tid < 16) {
        unsigned int h = (unsigned int)myrow * 2654435761u + 0x9E3779B9u;
        h ^= h>>16; h *= 0x85ebca6bu; h ^= h>>13; h *= 0xc2b2ae35u; h ^= h>>16;
        g_u[1][myrow] = (float)(h & 0xffffu) * (1.0f/65536.0f) + 0.0625f;
    }
    gbar(ep);

    float* svc = svbuf[0];
    float* svp = svbuf[1];
    {
        float p = 0.f;
        for (int i = tid; i < N; i += TPB) {
            float x = __ldcg(&g_u[1][i]);
            svc[i] = x;
            svp[i] = 0.f;
            p += x * x;
        }
        float n0 = block_sum(p, sred, sbc);
        float inv0 = rsqrtf(n0);
        for (int i = tid; i < N; i += TPB) svc[i] *= inv0;
        __syncthreads();
    }
    float beta_p = 0.f;

    for (int j = 0; j < KL; j++) {
        const int b = j & 1;
        const float4* M4  = ((const float4*)g_M) + (size_t)row * (N/4);
        const float4* sv4 = (const float4*)svc;
        float s = 0.f;
#pragma unroll
        for (int t = 0; t < 16; t++) {
            int qi = lane*2 + t*32;
            float4 m0 = M4[qi], m1 = M4[qi+1];
            float4 x0 = sv4[qi], x1 = sv4[qi+1];
            s += m0.x*x0.x + m0.y*x0.y + m0.z*x0.z + m0.w*x0.w
               + m1.x*x1.x + m1.y*x1.y + m1.z*x1.z + m1.w*x1.w;
        }
#pragma unroll
        for (int off = 8; off; off >>= 1) s += __shfl_down_sync(0xffffffffu, s, off, 16);
        if (lane == 0) shw[q] = s;
        __syncthreads();

        float pa = 0.f;
        if (tid < 16) {
            float uval = shw[tid];
            g_u[b][myrow] = uval;
            pa = uval * svc[myrow];
        }
#pragma unroll
        for (int off = 8; off; off >>= 1) pa += __shfl_down_sync(0xffffffffu, pa, off, 16);
        if (tid == 0) g_part[b][bid] = pa;
        gbar(ep);

        float alpha = sum_parts(g_part[b], sred, sbc);
        float pw = 0.f;
        for (int i = tid; i < N; i += TPB) {
            float w = __ldcg(&g_u[b][i]) - alpha*svc[i] - beta_p*svp[i];
            svp[i] = w;
            pw += w * w;
        }
        float nw = block_sum(pw, sred, sbc);
        float beta = sqrtf(fmaxf(nw, 1e-30f));
        if (bid == 0 && tid == 0) { g_alpha[j] = alpha; g_betav[j] = beta; }
        float invb = 1.0f / beta;
        for (int i = tid; i < N; i += TPB) svp[i] *= invb;
        __syncthreads();
        float* t = svc; svc = svp; svp = t;
        beta_p = beta;
    }
}

// ------- extremes: double Sturm count, 32-way multisection, 4 steps --------
__global__ void k_extremes(float* out) {
    __shared__ double sa[KL], sb[KL];
    __shared__ double sbounds[2];
    __shared__ double res[2];
    int tid = threadIdx.x;
    int warp = tid >> 5, lane = tid & 31;

    for (int i = tid; i < KL; i += 64) {
        sa[i] = (double)g_alpha[i];
        sb[i] = (double)g_betav[i];
    }
    __syncthreads();
    if (tid == 0) {
        double lo = 1e300, hi = -1e300;
        for (int i = 0; i < KL; i++) {
            double bl = (i > 0)    ? fabs(sb[i-1]) : 0.0;
            double br = (i < KL-1) ? fabs(sb[i])   : 0.0;
            double a = sa[i];
            if (a - bl - br < lo) lo = a - bl - br;
            if (a + bl + br > hi) hi = a + bl + br;
        }
        sbounds[0] = lo; sbounds[1] = hi;
    }
    __syncthreads();

    int target = (warp == 0) ? KL : 1;
    double lo = sbounds[0], hi = sbounds[1];

    for (int step = 0; step < 4; step++) {
        double w = (hi - lo) * (1.0 / 33.0);
        double x = lo + w * (double)(lane + 1);
        double d = sa[0] - x;
        int cnt = (d < 0.0);
        for (int i = 1; i < KL; i++) {
            double den = d;
            if (fabs(den) < 1e-280) den = (den < 0.0) ? -1e-280 : 1e-280;
            d = (sa[i] - x) - sb[i-1]*sb[i-1] / den;
            cnt += (d < 0.0);
        }
        unsigned mask = __ballot_sync(0xffffffffu, cnt >= target);
        int first = (mask == 0u) ? 32 : (__ffs(mask) - 1);
        if (first < 32) hi = lo + w * (double)(first + 1);
        lo = lo + w * (double)first;
    }
    if (lane == 0) res[warp] = 0.5 * (lo + hi);
    __syncthreads();
    if (tid == 0) {
        double lmax = fmax(res[0], 1e-12);
        double lmin = fmax(res[1], 1e-12);
        out[0] = (float)(log(lmax) - log(lmin));
    }
}

// ---------------- launch ------------------------------------------------------
extern "C" void kernel_launch(void* const* d_in, const int* in_sizes, int n_in,
                              void* d_out, int out_size) {
    const float* pred = (const float*)d_in[0];
    const float* scl  = (const float*)d_in[1];
    const float* Af   = (const float*)d_in[2];
    const int* frows  = (const int*)d_in[3];
    const int* fcols  = (const int*)d_in[4];
    float* out = (float*)d_out;

    k_prep <<<NNZ/TPB, TPB>>>(pred, scl);
    k_count<<<NNZ/TPB, TPB>>>(frows);
    k_scan <<<1, 256>>>();
    k_syrk <<<SYRK_TILES, 256>>>(Af);    // 4th launch -> captured by ncu
    k_fill <<<NNZ/TPB, TPB>>>(frows, fcols);

    k_spmm_AC <<<N, TPB>>>();
    k_tr_C_CT <<<dim3(64,64), dim3(32,8)>>>();
    k_spmm_M  <<<N, TPB>>>();

    k_lanczos <<<GRID, TPB>>>();
    k_extremes<<<1, 64>>>(out);
}

// round 14
// speedup vs baseline: 16.0709x; 1.1459x over previous
#include <cuda_runtime.h>
#include <cstdint>
#include <math.h>

#define N     2048
#define NNZ   32768
#define KL    56
#define GRID  128
#define TPB   256
#define BKS   16           // k-tile for SYRK
#define SYRK_TILES 136
#define SYRK_T 512

// ---------------- scratch (device globals; no allocation) ------------------
__device__ float g_A[N*N];
__device__ float g_C[N*N];
__device__ float g_CT[N*N];
__device__ float g_M[N*N];

__device__ float g_vals[NNZ];
__device__ int   g_rowptr[N+1];
__device__ int   g_cnt[N];
__device__ int   g_colidx[NNZ];
__device__ float g_csrval[NNZ];

__device__ float g_u[2][N];
__device__ float g_part[2][GRID];
__device__ float g_alpha[KL];
__device__ float g_betav[KL];
__device__ unsigned int g_barcnt;
__device__ volatile unsigned int g_release;

// ---------------- CSR build ------------------------------------------------
__global__ void k_prep(const float* __restrict__ pred, const float* __restrict__ scl) {
    int i = blockIdx.x * blockDim.x + threadIdx.x;
    if (i < NNZ) g_vals[i] = pred[i] * scl[i];
    if (i < N)   g_cnt[i] = 0;
    if (blockIdx.x == 0 && threadIdx.x == 0) { g_barcnt = 0; g_release = 0; }
}
__global__ void k_count(const int* __restrict__ rows) {
    int i = blockIdx.x * blockDim.x + threadIdx.x;
    if (i < NNZ) atomicAdd(&g_cnt[rows[i]], 1);
}
__global__ void k_scan() {
    int tid = threadIdx.x;
    int lane = tid & 31, warp = tid >> 5;
    int v[8]; int loc = 0;
#pragma unroll
    for (int u = 0; u < 8; u++) { v[u] = g_cnt[tid*8 + u]; loc += v[u]; }
    int sc = loc;
#pragma unroll
    for (int off = 1; off < 32; off <<= 1) {
        int nb = __shfl_up_sync(0xffffffffu, sc, off);
        if (lane >= off) sc += nb;
    }
    __shared__ int wsum[8];
    if (lane == 31) wsum[warp] = sc;
    __syncthreads();
    if (tid == 0) {
        int a = 0;
#pragma unroll
        for (int w = 0; w < 8; w++) { int t = wsum[w]; wsum[w] = a; a += t; }
    }
    __syncthreads();
    int run = sc - loc + wsum[warp];
#pragma unroll
    for (int u = 0; u < 8; u++) {
        g_rowptr[tid*8 + u] = run;
        g_cnt[tid*8 + u]    = run;
        run += v[u];
    }
    if (tid == 255) g_rowptr[N] = run;
}
__global__ void k_fill(const int* __restrict__ rows, const int* __restrict__ cols) {
    int i = blockIdx.x * blockDim.x + threadIdx.x;
    if (i < NNZ) {
        int p = atomicAdd(&g_cnt[rows[i]], 1);
        g_colidx[p] = cols[i];
        g_csrval[p] = g_vals[i];
    }
}

// ------ SYRK: A = Af*Af^T / N + I ------------------------------------------
// 136 CTAs, 512 threads (8x4 per thread), double-buffered, 1 sync per k-tile.
__global__ void __launch_bounds__(SYRK_T) k_syrk(const float* __restrict__ Af) {
    int rem = blockIdx.x, by = 0;
    while (rem >= 16 - by) { rem -= 16 - by; by++; }
    const int bx = by + rem;

    __shared__ __align__(16) float As[2][BKS][132];
    __shared__ __align__(16) float Bs[2][BKS][132];
    const int tid = threadIdx.x;
    const int tx = tid & 31, ty = tid >> 5;      // tx: col group (4 cols), ty: row group
    const int row0 = by * 128, col0 = bx * 128;

    uint64_t acc2[8][2];
#pragma unroll
    for (int i = 0; i < 8; i++) { acc2[i][0] = 0ull; acc2[i][1] = 0ull; }

    const int lr = tid >> 2;            // 0..127
    const int lk = (tid & 3) * 4;       // 0,4,8,12
    const float* abase = Af + (size_t)(row0 + lr) * N + lk;
    const float* bbase = Af + (size_t)(col0 + lr) * N + lk;

    float4 pa = *(const float4*)(abase);
    float4 pb = *(const float4*)(bbase);
    {   // stage tile 0 into buffer 0
        As[0][lk+0][lr]=pa.x; As[0][lk+1][lr]=pa.y; As[0][lk+2][lr]=pa.z; As[0][lk+3][lr]=pa.w;
        Bs[0][lk+0][lr]=pb.x; Bs[0][lk+1][lr]=pb.y; Bs[0][lk+2][lr]=pb.z; Bs[0][lk+3][lr]=pb.w;
    }
    __syncthreads();

    const int NIT = N / BKS;       // 128
    for (int it = 0; it < NIT; it++) {
        const int buf = it & 1;
        if (it + 1 < NIT) {
            int off = (it + 1) * BKS;
            pa = *(const float4*)(abase + off);
            pb = *(const float4*)(bbase + off);
        }
#pragma unroll
        for (int k = 0; k < BKS; k++) {
            float4 a0 = *(const float4*)&As[buf][k][4*ty];
            float4 a1 = *(const float4*)&As[buf][k][64+4*ty];
            const uint64_t* bq = (const uint64_t*)&Bs[buf][k][4*tx];
            uint64_t bp0 = bq[0], bp1 = bq[1];
            float av[8] = {a0.x,a0.y,a0.z,a0.w,a1.x,a1.y,a1.z,a1.w};
#pragma unroll
            for (int i = 0; i < 8; i++) {
                uint64_t ap;
                asm("mov.b64 %0, {%1, %1};" : "=l"(ap) : "f"(av[i]));
                asm("fma.rn.f32x2 %0, %1, %2, %0;" : "+l"(acc2[i][0]) : "l"(ap), "l"(bp0));
                asm("fma.rn.f32x2 %0, %1, %2, %0;" : "+l"(acc2[i][1]) : "l"(ap), "l"(bp1));
            }
        }
        if (it + 1 < NIT) {
            const int nb = buf ^ 1;
            As[nb][lk+0][lr]=pa.x; As[nb][lk+1][lr]=pa.y; As[nb][lk+2][lr]=pa.z; As[nb][lk+3][lr]=pa.w;
            Bs[nb][lk+0][lr]=pb.x; Bs[nb][lk+1][lr]=pb.y; Bs[nb][lk+2][lr]=pb.z; Bs[nb][lk+3][lr]=pb.w;
        }
        __syncthreads();
    }

    float acc[8][4];
#pragma unroll
    for (int i = 0; i < 8; i++)
#pragma unroll
        for (int j = 0; j < 2; j++) {
            float lo, hi;
            asm("mov.b64 {%0, %1}, %2;" : "=f"(lo), "=f"(hi) : "l"(acc2[i][j]));
            acc[i][2*j]   = lo;
            acc[i][2*j+1] = hi;
        }

    float invn = 1.0f / (float)N;
#pragma unroll
    for (int i = 0; i < 8; i++) {
        int gi = row0 + ((i<4) ? (4*ty+i) : (64+4*ty+i-4));
#pragma unroll
        for (int j = 0; j < 4; j++) {
            int gj = col0 + 4*tx + j;
            float val = acc[i][j]*invn + ((gi==gj)?1.0f:0.0f);
            g_A[(size_t)gi*N+gj] = val;
            if (bx > by) g_A[(size_t)gj*N+gi] = val;
        }
    }
}

// ---------------- SpMM 1: C = S * A ------------------------------------------
__global__ void k_spmm_AC() {
    int r = blockIdx.x, t = threadIdx.x;
    int s = g_rowptr[r], e = g_rowptr[r+1];
    float acc[8] = {0,0,0,0,0,0,0,0};
    for (int k = s; k < e; k++) {
        int c = g_colidx[k];
        float v = g_csrval[k];
        const float* xr = g_A + (size_t)c * N;
#pragma unroll
        for (int u = 0; u < 8; u++) acc[u] += v * xr[t + u*TPB];
    }
    float* yr = g_C + (size_t)r * N;
#pragma unroll
    for (int u = 0; u < 8; u++) yr[t + u*TPB] = acc[u];
}

// ---------------- transpose: CT = C^T ----------------------------------------
__global__ void k_tr_C_CT() {
    __shared__ float t[32][33];
    int bx = blockIdx.x*32, by = blockIdx.y*32;
    int x = bx + threadIdx.x;
#pragma unroll
    for (int j = 0; j < 32; j += 8)
        t[threadIdx.y+j][threadIdx.x] = g_C[(size_t)(by+threadIdx.y+j)*N + x];
    __syncthreads();
    int x2 = by + threadIdx.x;
#pragma unroll
    for (int j = 0; j < 32; j += 8)
        g_CT[(size_t)(bx+threadIdx.y+j)*N + x2] = t[threadIdx.x][threadIdx.y+j];
}

// ------- SpMM 2 fused: M = A + C + C^T + S*C^T ------------------------------
__global__ void k_spmm_M() {
    int r = blockIdx.x, t = threadIdx.x;
    int s = g_rowptr[r], e = g_rowptr[r+1];
    float acc[8] = {0,0,0,0,0,0,0,0};
    for (int k = s; k < e; k++) {
        int c = g_colidx[k];
        float v = g_csrval[k];
        const float* xr = g_CT + (size_t)c * N;
#pragma unroll
        for (int u = 0; u < 8; u++) acc[u] += v * xr[t + u*TPB];
    }
    const float* ar = g_A  + (size_t)r * N;
    const float* cr = g_C  + (size_t)r * N;
    const float* tr = g_CT + (size_t)r * N;
    float* mr = g_M + (size_t)r * N;
#pragma unroll
    for (int u = 0; u < 8; u++) {
        int i = t + u*TPB;
        mr[i] = ar[i] + cr[i] + tr[i] + acc[u];
    }
}

// ---------------- Lanczos: persistent, atomic-counter grid barrier ---------
__device__ __forceinline__ void gbar(unsigned int& ep) {
    ep++;
    __threadfence();
    __syncthreads();
    if (threadIdx.x == 0) {
        unsigned int old = atomicAdd(&g_barcnt, 1u);
        if (old == GRID - 1u) {
            g_barcnt = 0;
            __threadfence();
            g_release = ep;
        } else {
            while (g_release < ep) { }
        }
    }
    __syncthreads();
    __threadfence();
}

__device__ __forceinline__ float sum_parts(const float* part, float* sred, float* sbc) {
    int tid = threadIdx.x, warp = tid >> 5, wl = tid & 31;
    float a = (tid < GRID) ? __ldcg(&part[tid]) : 0.f;
#pragma unroll
    for (int off = 16; off; off >>= 1) a += __shfl_down_sync(0xffffffffu, a, off);
    if (wl == 0) sred[warp] = a;
    __syncthreads();
    if (tid == 0) {
        float s = 0.f;
#pragma unroll
        for (int w = 0; w < 4; w++) s += sred[w];
        sbc[0] = s;
    }
    __syncthreads();
    return sbc[0];
}

__device__ __forceinline__ float block_sum(float p, float* sred, float* sbc) {
    int tid = threadIdx.x, warp = tid >> 5, wl = tid & 31;
#pragma unroll
    for (int off = 16; off; off >>= 1) p += __shfl_down_sync(0xffffffffu, p, off);
    if (wl == 0) sred[warp] = p;
    __syncthreads();
    if (tid == 0) {
        float s = 0.f;
#pragma unroll
        for (int w = 0; w < 8; w++) s += sred[w];
        sbc[0] = s;
    }
    __syncthreads();
    return sbc[0];
}

__global__ void __launch_bounds__(TPB) k_lanczos() {
    __shared__ __align__(16) float svbuf[2][N];
    __shared__ float shw[16];
    __shared__ float sred[8];
    __shared__ float sbc[1];

    const int tid = threadIdx.x, bid = blockIdx.x;
    const int q = tid >> 4, lane = tid & 15;
    const int row = bid*16 + q;
    const int myrow = bid*16 + tid;
    unsigned int ep = 0;

    if (tid < 16) {
        unsigned int h = (unsigned int)myrow * 2654435761u + 0x9E3779B9u;
        h ^= h>>16; h *= 0x85ebca6bu; h ^= h>>13; h *= 0xc2b2ae35u; h ^= h>>16;
        g_u[1][myrow] = (float)(h & 0xffffu) * (1.0f/65536.0f) + 0.0625f;
    }
    gbar(ep);

    float* svc = svbuf[0];
    float* svp = svbuf[1];
    {
        float p = 0.f;
        for (int i = tid; i < N; i += TPB) {
            float x = __ldcg(&g_u[1][i]);
            svc[i] = x;
            svp[i] = 0.f;
            p += x * x;
        }
        float n0 = block_sum(p, sred, sbc);
        float inv0 = rsqrtf(n0);
        for (int i = tid; i < N; i += TPB) svc[i] *= inv0;
        __syncthreads();
    }
    float beta_p = 0.f;

    for (int j = 0; j < KL; j++) {
        const int b = j & 1;
        const float4* M4  = ((const float4*)g_M) + (size_t)row * (N/4);
        const float4* sv4 = (const float4*)svc;
        float s = 0.f;
#pragma unroll
        for (int t = 0; t < 16; t++) {
            int qi = lane*2 + t*32;
            float4 m0 = M4[qi], m1 = M4[qi+1];
            float4 x0 = sv4[qi], x1 = sv4[qi+1];
            s += m0.x*x0.x + m0.y*x0.y + m0.z*x0.z + m0.w*x0.w
               + m1.x*x1.x + m1.y*x1.y + m1.z*x1.z + m1.w*x1.w;
        }
#pragma unroll
        for (int off = 8; off; off >>= 1) s += __shfl_down_sync(0xffffffffu, s, off, 16);
        if (lane == 0) shw[q] = s;
        __syncthreads();

        float pa = 0.f;
        if (tid < 16) {
            float uval = shw[tid];
            g_u[b][myrow] = uval;
            pa = uval * svc[myrow];
        }
#pragma unroll
        for (int off = 8; off; off >>= 1) pa += __shfl_down_sync(0xffffffffu, pa, off, 16);
        if (tid == 0) g_part[b][bid] = pa;
        gbar(ep);

        float alpha = sum_parts(g_part[b], sred, sbc);
        float pw = 0.f;
        for (int i = tid; i < N; i += TPB) {
            float w = __ldcg(&g_u[b][i]) - alpha*svc[i] - beta_p*svp[i];
            svp[i] = w;
            pw += w * w;
        }
        float nw = block_sum(pw, sred, sbc);
        float beta = sqrtf(fmaxf(nw, 1e-30f));
        if (bid == 0 && tid == 0) { g_alpha[j] = alpha; g_betav[j] = beta; }
        float invb = 1.0f / beta;
        for (int i = tid; i < N; i += TPB) svp[i] *= invb;
        __syncthreads();
        float* t = svc; svc = svp; svp = t;
        beta_p = beta;
    }
}

// ------- extremes: double Sturm count, 32-way multisection, 4 steps --------
__global__ void k_extremes(float* out) {
    __shared__ double sa[KL], sb[KL];
    __shared__ double sbounds[2];
    __shared__ double res[2];
    int tid = threadIdx.x;
    int warp = tid >> 5, lane = tid & 31;

    for (int i = tid; i < KL; i += 64) {
        sa[i] = (double)g_alpha[i];
        sb[i] = (double)g_betav[i];
    }
    __syncthreads();
    if (tid == 0) {
        double lo = 1e300, hi = -1e300;
        for (int i = 0; i < KL; i++) {
            double bl = (i > 0)    ? fabs(sb[i-1]) : 0.0;
            double br = (i < KL-1) ? fabs(sb[i])   : 0.0;
            double a = sa[i];
            if (a - bl - br < lo) lo = a - bl - br;
            if (a + bl + br > hi) hi = a + bl + br;
        }
        sbounds[0] = lo; sbounds[1] = hi;
    }
    __syncthreads();

    int target = (warp == 0) ? KL : 1;
    double lo = sbounds[0], hi = sbounds[1];

    for (int step = 0; step < 4; step++) {
        double w = (hi - lo) * (1.0 / 33.0);
        double x = lo + w * (double)(lane + 1);
        double d = sa[0] - x;
        int cnt = (d < 0.0);
        for (int i = 1; i < KL; i++) {
            double den = d;
            if (fabs(den) < 1e-280) den = (den < 0.0) ? -1e-280 : 1e-280;
            d = (sa[i] - x) - sb[i-1]*sb[i-1] / den;
            cnt += (d < 0.0);
        }
        unsigned mask = __ballot_sync(0xffffffffu, cnt >= target);
        int first = (mask == 0u) ? 32 : (__ffs(mask) - 1);
        if (first < 32) hi = lo + w * (double)(first + 1);
        lo = lo + w * (double)first;
    }
    if (lane == 0) res[warp] = 0.5 * (lo + hi);
    __syncthreads();
    if (tid == 0) {
        double lmax = fmax(res[0], 1e-12);
        double lmin = fmax(res[1], 1e-12);
        out[0] = (float)(log(lmax) - log(lmin));
    }
}

// ---------------- launch ------------------------------------------------------
extern "C" void kernel_launch(void* const* d_in, const int* in_sizes, int n_in,
                              void* d_out, int out_size) {
    const float* pred = (const float*)d_in[0];
    const float* scl  = (const float*)d_in[1];
    const float* Af   = (const float*)d_in[2];
    const int* frows  = (const int*)d_in[3];
    const int* fcols  = (const int*)d_in[4];
    float* out = (float*)d_out;

    k_prep <<<NNZ/TPB, TPB>>>(pred, scl);
    k_count<<<NNZ/TPB, TPB>>>(frows);
    k_scan <<<1, 256>>>();
    k_syrk <<<SYRK_TILES, SYRK_T>>>(Af);   // 4th launch -> captured by ncu
    k_fill <<<NNZ/TPB, TPB>>>(frows, fcols);

    k_spmm_AC <<<N, TPB>>>();
    k_tr_C_CT <<<dim3(64,64), dim3(32,8)>>>();
    k_spmm_M  <<<N, TPB>>>();

    k_lanczos <<<GRID, TPB>>>();
    k_extremes<<<1, 64>>>(out);
}